// round 1
// baseline (speedup 1.0000x reference)
#include <cuda_runtime.h>
#include <cuda_bf16.h>
#include <stdint.h>

// ---------------------------------------------------------------------------
// GCN2: out = GCNConv(relu(GCNConv(x, W1, b1)), W2, b2)
//   GCNConv(x,W,b): h = xW;  deg = 1 + indeg;  dinv = rsqrt(deg)
//     out[d] = sum_{(s,d) in E} dinv[s]*dinv[d]*h[s]  +  dinv[d]^2 * h[d]  + b
// Shapes: N=100000, F=64, H=128, C=40, E=1600000
// ---------------------------------------------------------------------------

#define NMAX 100000
#define EMAX 1600000
#define F_IN 64
#define HID  128
#define COUT 40

__device__ float g_deg[NMAX];
__device__ float g_dinv[NMAX];
__device__ float g_h1[(size_t)NMAX * HID];
__device__ float g_agg1[(size_t)NMAX * HID];
__device__ float g_h2[(size_t)NMAX * COUT];
__device__ int   g_is64;

// ---------------------------------------------------------------------------
// Index dtype detection: reference says int64 but JAX w/o x64 emits int32.
// If int64 (values < 2^31), every odd 32-bit word is 0. For random int32 data
// in [0,1e5) the probability of 32 consecutive odd words being zero is ~0.
// ---------------------------------------------------------------------------
__global__ void k_detect_dtype(const int* __restrict__ edge_words) {
    if (threadIdx.x == 0) {
        int all_zero = 1;
        #pragma unroll
        for (int i = 0; i < 32; i++) {
            if (edge_words[2 * i + 1] != 0) all_zero = 0;
        }
        g_is64 = all_zero;
    }
}

__device__ __forceinline__ long long load_idx(const void* p, long long i, int is64) {
    if (is64) return ((const long long*)p)[i];
    return (long long)((const int*)p)[i];
}

// ---------------------------------------------------------------------------
// Degree / dinv
// ---------------------------------------------------------------------------
__global__ void k_init_deg(float* deg, int N) {
    int i = blockIdx.x * blockDim.x + threadIdx.x;
    if (i < N) deg[i] = 1.0f;  // self loop
}

__global__ void k_deg(const void* __restrict__ edges, float* deg, int E) {
    int e = blockIdx.x * blockDim.x + threadIdx.x;
    if (e >= E) return;
    int is64 = g_is64;
    long long d = load_idx(edges, (long long)E + e, is64);
    atomicAdd(&deg[d], 1.0f);
}

__global__ void k_dinv(const float* __restrict__ deg, float* dinv, int N) {
    int i = blockIdx.x * blockDim.x + threadIdx.x;
    if (i < N) {
        float dg = deg[i];
        dinv[i] = dg > 0.f ? rsqrtf(dg) : 0.f;
    }
}

// ---------------------------------------------------------------------------
// GEMM1: H[N,128] = X[N,64] @ W[64,128]
// block = 256 threads, 64 rows/block. thread (r = tid>>2, cg = tid&3) owns
// columns {16*j + 4*cg .. +3 | j<8}  (interleaved -> conflict-free LDS.128)
// ---------------------------------------------------------------------------
__global__ void k_gemm1(const float* __restrict__ X, const float* __restrict__ W,
                        float* __restrict__ H, int N) {
    extern __shared__ float sm[];
    float* xs = sm;                 // 64 x 65 (padded)
    float* ws = sm + 64 * 65;       // 64 x 128
    const int tid = threadIdx.x;
    const int row0 = blockIdx.x * 64;

    // load W1 (8192 floats = 2048 float4)
    const float4* W4 = (const float4*)W;
    float4* ws4 = (float4*)ws;
    #pragma unroll
    for (int i = tid; i < 2048; i += 256) ws4[i] = W4[i];

    // load X tile with +1 pad
    int rows = min(64, N - row0);
    const float4* X4 = (const float4*)(X + (size_t)row0 * F_IN);
    for (int i = tid; i < rows * 16; i += 256) {
        int r = i >> 4, c4 = i & 15;
        float4 v = X4[i];
        float* p = xs + r * 65 + c4 * 4;
        p[0] = v.x; p[1] = v.y; p[2] = v.z; p[3] = v.w;
    }
    __syncthreads();

    int r = tid >> 2, cg = tid & 3;
    if (row0 + r >= N) return;

    float4 acc[8];
    #pragma unroll
    for (int j = 0; j < 8; j++) acc[j] = make_float4(0.f, 0.f, 0.f, 0.f);

    const float* xr = xs + r * 65;
    #pragma unroll 4
    for (int k = 0; k < 64; k++) {
        float a = xr[k];
        const float* wk = ws + k * 128 + cg * 4;
        #pragma unroll
        for (int j = 0; j < 8; j++) {
            float4 w = *(const float4*)(wk + j * 16);
            acc[j].x += a * w.x; acc[j].y += a * w.y;
            acc[j].z += a * w.z; acc[j].w += a * w.w;
        }
    }
    float* o = H + (size_t)(row0 + r) * HID + cg * 4;
    #pragma unroll
    for (int j = 0; j < 8; j++) *(float4*)(o + j * 16) = acc[j];
}

// ---------------------------------------------------------------------------
// agg1 init with self-loop term: agg1[n,:] = dinv[n]^2 * h1[n,:]
// ---------------------------------------------------------------------------
__global__ void k_init_agg1(const float* __restrict__ h1, const float* __restrict__ dinv,
                            float* __restrict__ agg, int N) {
    int i = blockIdx.x * blockDim.x + threadIdx.x;  // float4 index, 32 per row
    if (i >= N * 32) return;
    int n = i >> 5;
    float w = dinv[n]; w = w * w;
    float4 v = ((const float4*)h1)[i];
    v.x *= w; v.y *= w; v.z *= w; v.w *= w;
    ((float4*)agg)[i] = v;
}

// ---------------------------------------------------------------------------
// Scatter layer 1: one warp per edge, 32 float4 lanes cover 128 features.
// ---------------------------------------------------------------------------
__device__ __forceinline__ void red_add_v4(float* p, float4 v) {
    unsigned long long gp = __cvta_generic_to_global(p);
    asm volatile("red.global.add.v4.f32 [%0], {%1,%2,%3,%4};"
                 :: "l"(gp), "f"(v.x), "f"(v.y), "f"(v.z), "f"(v.w)
                 : "memory");
}

__global__ void k_scatter1(const void* __restrict__ edges, const float* __restrict__ dinv,
                           const float* __restrict__ h1, float* __restrict__ agg, int E) {
    int e = (blockIdx.x * blockDim.x + threadIdx.x) >> 5;
    int lane = threadIdx.x & 31;
    if (e >= E) return;
    int is64 = g_is64;
    long long s = load_idx(edges, e, is64);
    long long d = load_idx(edges, (long long)E + e, is64);
    float nrm = dinv[s] * dinv[d];
    float4 v = ((const float4*)(h1 + (size_t)s * HID))[lane];
    v.x *= nrm; v.y *= nrm; v.z *= nrm; v.w *= nrm;
    red_add_v4(agg + (size_t)d * HID + lane * 4, v);
}

// ---------------------------------------------------------------------------
// GEMM2: H2[N,40] = relu(agg1 + b1)[N,128] @ W2[128,40]
// block = 128 threads, 64 rows/block; thread (r = tid>>1, cg = tid&1) owns
// 20 contiguous columns as 5 float4.
// ---------------------------------------------------------------------------
__global__ void k_gemm2(const float* __restrict__ A, const float* __restrict__ W,
                        const float* __restrict__ b1, float* __restrict__ H2, int N) {
    extern __shared__ float sm[];
    float* xs = sm;                  // 64 x 129 (padded)
    float* ws = sm + 64 * 129;       // 128 x 40
    const int tid = threadIdx.x;
    const int row0 = blockIdx.x * 64;

    // load W2 (5120 floats = 1280 float4)
    const float4* W4 = (const float4*)W;
    float4* ws4 = (float4*)ws;
    #pragma unroll
    for (int i = tid; i < 1280; i += 128) ws4[i] = W4[i];

    // load A tile, fused bias + relu
    int rows = min(64, N - row0);
    const float4* A4 = (const float4*)(A + (size_t)row0 * HID);
    for (int i = tid; i < rows * 32; i += 128) {
        int r = i >> 5, c4 = i & 31;
        float4 v = A4[i];
        float4 bb = ((const float4*)b1)[c4];
        v.x = fmaxf(v.x + bb.x, 0.f);
        v.y = fmaxf(v.y + bb.y, 0.f);
        v.z = fmaxf(v.z + bb.z, 0.f);
        v.w = fmaxf(v.w + bb.w, 0.f);
        float* p = xs + r * 129 + c4 * 4;
        p[0] = v.x; p[1] = v.y; p[2] = v.z; p[3] = v.w;
    }
    __syncthreads();

    int r = tid >> 1, cg = tid & 1;
    if (row0 + r >= N) return;

    float4 acc[5];
    #pragma unroll
    for (int j = 0; j < 5; j++) acc[j] = make_float4(0.f, 0.f, 0.f, 0.f);

    const float* xr = xs + r * 129;
    #pragma unroll 4
    for (int k = 0; k < 128; k++) {
        float a = xr[k];
        const float* wk = ws + k * COUT + cg * 20;
        #pragma unroll
        for (int j = 0; j < 5; j++) {
            float4 w = *(const float4*)(wk + j * 4);
            acc[j].x += a * w.x; acc[j].y += a * w.y;
            acc[j].z += a * w.z; acc[j].w += a * w.w;
        }
    }
    float* o = H2 + (size_t)(row0 + r) * COUT + cg * 20;
    #pragma unroll
    for (int j = 0; j < 5; j++) *(float4*)(o + j * 4) = acc[j];
}

// ---------------------------------------------------------------------------
// out init: out[n,:] = dinv[n]^2 * h2[n,:] + b2
// ---------------------------------------------------------------------------
__global__ void k_init_out(const float* __restrict__ h2, const float* __restrict__ dinv,
                           const float* __restrict__ b2, float* __restrict__ out, int N) {
    int i = blockIdx.x * blockDim.x + threadIdx.x;  // float4 index, 10 per row
    if (i >= N * 10) return;
    int n = i / 10;
    int j = i - n * 10;
    float w = dinv[n]; w = w * w;
    float4 v = ((const float4*)h2)[i];
    float4 bb = ((const float4*)b2)[j];
    v.x = v.x * w + bb.x; v.y = v.y * w + bb.y;
    v.z = v.z * w + bb.z; v.w = v.w * w + bb.w;
    ((float4*)out)[i] = v;
}

// ---------------------------------------------------------------------------
// Scatter layer 2: thread per (edge, float4-of-10) pair.
// ---------------------------------------------------------------------------
__global__ void k_scatter2(const void* __restrict__ edges, const float* __restrict__ dinv,
                           const float* __restrict__ h2, float* __restrict__ out, int E) {
    int idx = blockIdx.x * blockDim.x + threadIdx.x;
    if (idx >= E * 10) return;
    int e = idx / 10;
    int j = idx - e * 10;
    int is64 = g_is64;
    long long s = load_idx(edges, e, is64);
    long long d = load_idx(edges, (long long)E + e, is64);
    float nrm = dinv[s] * dinv[d];
    float4 v = ((const float4*)(h2 + (size_t)s * COUT))[j];
    v.x *= nrm; v.y *= nrm; v.z *= nrm; v.w *= nrm;
    red_add_v4(out + (size_t)d * COUT + j * 4, v);
}

// ---------------------------------------------------------------------------
// Launch
// ---------------------------------------------------------------------------
extern "C" void kernel_launch(void* const* d_in, const int* in_sizes, int n_in,
                              void* d_out, int out_size) {
    const float* x     = (const float*)d_in[0];
    const void*  edges = d_in[1];
    const float* W1    = (const float*)d_in[2];
    const float* b1    = (const float*)d_in[3];
    const float* W2    = (const float*)d_in[4];
    const float* b2    = (const float*)d_in[5];
    float* out = (float*)d_out;

    const int N = in_sizes[0] / F_IN;
    const int E = in_sizes[1] / 2;

    float *deg, *dinv, *h1, *agg1, *h2;
    cudaGetSymbolAddress((void**)&deg,  g_deg);
    cudaGetSymbolAddress((void**)&dinv, g_dinv);
    cudaGetSymbolAddress((void**)&h1,   g_h1);
    cudaGetSymbolAddress((void**)&agg1, g_agg1);
    cudaGetSymbolAddress((void**)&h2,   g_h2);

    const int gemm1_smem = (64 * 65 + 64 * 128) * 4;   // 49408
    const int gemm2_smem = (64 * 129 + 128 * 40) * 4;  // 53504
    cudaFuncSetAttribute(k_gemm1, cudaFuncAttributeMaxDynamicSharedMemorySize, gemm1_smem);
    cudaFuncSetAttribute(k_gemm2, cudaFuncAttributeMaxDynamicSharedMemorySize, gemm2_smem);

    k_detect_dtype<<<1, 32>>>((const int*)edges);

    k_init_deg<<<(N + 255) / 256, 256>>>(deg, N);
    k_deg<<<(E + 255) / 256, 256>>>(edges, deg, E);
    k_dinv<<<(N + 255) / 256, 256>>>(deg, dinv, N);

    k_gemm1<<<(N + 63) / 64, 256, gemm1_smem>>>(x, W1, h1, N);
    k_init_agg1<<<(N * 32 + 255) / 256, 256>>>(h1, dinv, agg1, N);
    k_scatter1<<<(int)(((long long)E * 32 + 255) / 256), 256>>>(edges, dinv, h1, agg1, E);

    k_gemm2<<<(N + 63) / 64, 128, gemm2_smem>>>(agg1, W2, b1, h2, N);
    k_init_out<<<(N * 10 + 255) / 256, 256>>>(h2, dinv, b2, out, N);
    k_scatter2<<<(int)(((long long)E * 10 + 255) / 256), 256>>>(edges, dinv, h2, out, E);
}

// round 2
// speedup vs baseline: 1.5557x; 1.5557x over previous
#include <cuda_runtime.h>
#include <cuda_bf16.h>
#include <stdint.h>

// ---------------------------------------------------------------------------
// GCN2: out = GCNConv(relu(GCNConv(x, W1, b1)), W2, b2)
// Reordered layer 1:  h = relu( (Â·X)·W1 + b1 )   (scatter in 64-dim space)
// Layer 2:            out = Â·(h·W2) + b2          (scatter in 40-dim space)
// Â x = sum_edges dinv[s]dinv[d] x[s] + dinv[d]^2 x[d]
// Shapes: N=100000, F=64, H=128, C=40, E=1600000
// ---------------------------------------------------------------------------

#define NMAX 100032
#define EMAX 1600000
#define F_IN 64
#define HID  128
#define COUT 40

__device__ float g_deg[NMAX];
__device__ float g_dinv[NMAX];
__device__ int2  g_edges[EMAX];
__device__ float g_aggx[(size_t)NMAX * F_IN];
__device__ float g_h2[(size_t)NMAX * COUT];
__device__ int   g_is64;

// ---------------------------------------------------------------------------
// helpers
// ---------------------------------------------------------------------------
__device__ __forceinline__ void red_add_v4(float* p, float4 v) {
    unsigned long long gp = __cvta_generic_to_global(p);
    asm volatile("red.global.add.v4.f32 [%0], {%1,%2,%3,%4};"
                 :: "l"(gp), "f"(v.x), "f"(v.y), "f"(v.z), "f"(v.w)
                 : "memory");
}
__device__ __forceinline__ void red_add_f32(float* p, float v) {
    unsigned long long gp = __cvta_generic_to_global(p);
    asm volatile("red.global.add.f32 [%0], %1;" :: "l"(gp), "f"(v) : "memory");
}

// ---------------------------------------------------------------------------
// (0) dtype detect: int64 indices have all-zero odd words (values < 2^31)
// ---------------------------------------------------------------------------
__global__ void k_detect_dtype(const int* __restrict__ edge_words) {
    if (threadIdx.x == 0) {
        int all_zero = 1;
        #pragma unroll
        for (int i = 0; i < 32; i++)
            if (edge_words[2 * i + 1] != 0) all_zero = 0;
        g_is64 = all_zero;
    }
}

// (1) deg init (self loop)
__global__ void k_init_deg(float* deg, int N) {
    int i = blockIdx.x * blockDim.x + threadIdx.x;
    if (i < N) deg[i] = 1.0f;
}

// (2) convert indices to int2 + accumulate degrees
__global__ void k_conv_deg(const void* __restrict__ edges_raw, int2* __restrict__ edges,
                           float* __restrict__ deg, int E) {
    int e = blockIdx.x * blockDim.x + threadIdx.x;
    if (e >= E) return;
    int s, d;
    if (g_is64) {
        s = (int)((const long long*)edges_raw)[e];
        d = (int)((const long long*)edges_raw)[(long long)E + e];
    } else {
        s = ((const int*)edges_raw)[e];
        d = ((const int*)edges_raw)[(long long)E + e];
    }
    edges[e] = make_int2(s, d);
    red_add_f32(&deg[d], 1.0f);
}

// (3) dinv
__global__ void k_dinv(const float* __restrict__ deg, float* dinv, int N) {
    int i = blockIdx.x * blockDim.x + threadIdx.x;
    if (i < N) {
        float dg = deg[i];
        dinv[i] = dg > 0.f ? rsqrtf(dg) : 0.f;
    }
}

// (4) aggx init with self-loop term: aggx[n,:] = dinv[n]^2 * x[n,:]
__global__ void k_init_aggx(const float* __restrict__ x, const float* __restrict__ dinv,
                            float* __restrict__ agg, int N) {
    int i = blockIdx.x * blockDim.x + threadIdx.x;  // float4 index, 16 per row
    if (i >= N * 16) return;
    int n = i >> 4;
    float w = dinv[n]; w = w * w;
    float4 v = ((const float4*)x)[i];
    v.x *= w; v.y *= w; v.z *= w; v.w *= w;
    ((float4*)agg)[i] = v;
}

// (5) scatter X: 16 lanes per edge cover 64 features (16 float4)
__global__ void k_scatter_x(const int2* __restrict__ edges, const float* __restrict__ dinv,
                            const float* __restrict__ x, float* __restrict__ agg, int E) {
    int t = blockIdx.x * blockDim.x + threadIdx.x;
    int e = t >> 4;
    int lane = t & 15;
    if (e >= E) return;
    int2 ed = edges[e];
    float nrm = __ldg(&dinv[ed.x]) * __ldg(&dinv[ed.y]);
    float4 v = ((const float4*)(x + (size_t)ed.x * F_IN))[lane];
    v.x *= nrm; v.y *= nrm; v.z *= nrm; v.w *= nrm;
    red_add_v4(agg + (size_t)ed.y * F_IN + lane * 4, v);
}

// ---------------------------------------------------------------------------
// (6) fused GEMM: h2 = relu(aggx*W1 + b1) * W2 ; out_init = dinv^2*h2 + b2
// 256-row tile, 256 threads, 4 rows/thread.
// phase1: thread (r0 = tid>>2, cg = tid&3) owns rows {r0+64m} x cols {16j+4cg..+3}
// phase2: same rows x cols [cg*10, cg*10+10)
// ---------------------------------------------------------------------------
#define XS_STRIDE 68    // 64 + 4 pad
#define HS_STRIDE 132   // 128 + 4 pad
// smem layout (floats):
//   phase1: xs[256*68]=17408 | ws1[64*128]=8192          (25600 fl)
//   phase2: hs[256*132]=33792 | w2t[40*132]=5280          (39072 fl = 156288 B)
#define SMEM_FLOATS 39072

__global__ void __launch_bounds__(256, 1)
k_fused_gemm(const float* __restrict__ A, const float* __restrict__ W1,
             const float* __restrict__ b1, const float* __restrict__ W2,
             const float* __restrict__ b2, const float* __restrict__ dinv,
             float* __restrict__ h2, float* __restrict__ out, int N) {
    extern __shared__ float sm[];
    float* xs  = sm;                 // 256 x 68
    float* ws1 = sm + 256 * XS_STRIDE;
    float* hs  = sm;                 // 256 x 132 (aliases xs/ws1, used after sync)
    float* w2t = sm + 256 * HS_STRIDE;

    const int tid = threadIdx.x;
    const int row0 = blockIdx.x * 256;
    const int rows = min(256, N - row0);
    const int r0 = tid >> 2, cg = tid & 3;

    // load W1 (64x128 = 2048 float4)
    {
        const float4* W4 = (const float4*)W1;
        #pragma unroll
        for (int i = tid; i < 2048; i += 256)
            *(float4*)(ws1 + (i >> 5) * 128 + (i & 31) * 4) = W4[i];
    }
    // load A tile (rows x 64), zero-pad missing rows
    {
        const float4* A4 = (const float4*)(A + (size_t)row0 * F_IN);
        for (int i = tid; i < rows * 16; i += 256) {
            int r = i >> 4, c4 = i & 15;
            *(float4*)(xs + r * XS_STRIDE + c4 * 4) = A4[i];
        }
        float4 z = make_float4(0.f, 0.f, 0.f, 0.f);
        for (int i = rows * 16 + tid; i < 256 * 16; i += 256) {
            int r = i >> 4, c4 = i & 15;
            *(float4*)(xs + r * XS_STRIDE + c4 * 4) = z;
        }
    }
    __syncthreads();

    // phase 1: acc[m][j] : rows r0+64m, cols 16j+4cg
    float4 acc[4][8];
    #pragma unroll
    for (int m = 0; m < 4; m++)
        #pragma unroll
        for (int j = 0; j < 8; j++) acc[m][j] = make_float4(0.f, 0.f, 0.f, 0.f);

    #pragma unroll 2
    for (int k = 0; k < 64; k++) {
        float4 w[8];
        const float* wk = ws1 + k * 128 + cg * 4;
        #pragma unroll
        for (int j = 0; j < 8; j++) w[j] = *(const float4*)(wk + j * 16);
        #pragma unroll
        for (int m = 0; m < 4; m++) {
            float a = xs[(r0 + 64 * m) * XS_STRIDE + k];
            #pragma unroll
            for (int j = 0; j < 8; j++) {
                acc[m][j].x += a * w[j].x; acc[m][j].y += a * w[j].y;
                acc[m][j].z += a * w[j].z; acc[m][j].w += a * w[j].w;
            }
        }
    }

    // bias + relu
    {
        float4 bb[8];
        #pragma unroll
        for (int j = 0; j < 8; j++) bb[j] = *(const float4*)(b1 + 16 * j + 4 * cg);
        #pragma unroll
        for (int m = 0; m < 4; m++)
            #pragma unroll
            for (int j = 0; j < 8; j++) {
                acc[m][j].x = fmaxf(acc[m][j].x + bb[j].x, 0.f);
                acc[m][j].y = fmaxf(acc[m][j].y + bb[j].y, 0.f);
                acc[m][j].z = fmaxf(acc[m][j].z + bb[j].z, 0.f);
                acc[m][j].w = fmaxf(acc[m][j].w + bb[j].w, 0.f);
            }
    }

    __syncthreads();  // all phase-1 smem reads done; hs may now alias xs/ws1

    // write h tile to hs
    #pragma unroll
    for (int m = 0; m < 4; m++)
        #pragma unroll
        for (int j = 0; j < 8; j++)
            *(float4*)(hs + (r0 + 64 * m) * HS_STRIDE + 16 * j + 4 * cg) = acc[m][j];

    // load W2 transposed: w2t[c][k] = W2[k][c]
    for (int i = tid; i < HID * COUT; i += 256) {
        int k = i / COUT, c = i - k * COUT;
        w2t[c * HS_STRIDE + k] = W2[i];
    }
    __syncthreads();

    // phase 2: out cols [cg*10, cg*10+10)
    float acc2[4][10];
    #pragma unroll
    for (int m = 0; m < 4; m++)
        #pragma unroll
        for (int i = 0; i < 10; i++) acc2[m][i] = 0.f;

    for (int k = 0; k < 128; k += 4) {
        float4 a[4];
        #pragma unroll
        for (int m = 0; m < 4; m++)
            a[m] = *(const float4*)(hs + (r0 + 64 * m) * HS_STRIDE + k);
        #pragma unroll
        for (int i = 0; i < 10; i++) {
            float4 w = *(const float4*)(w2t + (cg * 10 + i) * HS_STRIDE + k);
            #pragma unroll
            for (int m = 0; m < 4; m++) {
                acc2[m][i] += a[m].x * w.x + a[m].y * w.y
                            + a[m].z * w.z + a[m].w * w.w;
            }
        }
    }

    // store h2 and out_init = dinv^2 * h2 + b2
    #pragma unroll
    for (int m = 0; m < 4; m++) {
        int row = row0 + r0 + 64 * m;
        if (row >= N) continue;
        float dv = dinv[row]; dv = dv * dv;
        #pragma unroll
        for (int i = 0; i < 10; i++) {
            int c = cg * 10 + i;
            float v = acc2[m][i];
            h2[(size_t)row * COUT + c]  = v;
            out[(size_t)row * COUT + c] = dv * v + b2[c];
        }
    }
}

// (7) scatter layer 2: thread per (edge, float4-of-10)
__global__ void k_scatter2(const int2* __restrict__ edges, const float* __restrict__ dinv,
                           const float* __restrict__ h2, float* __restrict__ out, int E) {
    int idx = blockIdx.x * blockDim.x + threadIdx.x;
    if (idx >= E * 10) return;
    int e = idx / 10;
    int j = idx - e * 10;
    int2 ed = edges[e];
    float nrm = __ldg(&dinv[ed.x]) * __ldg(&dinv[ed.y]);
    float4 v = ((const float4*)(h2 + (size_t)ed.x * COUT))[j];
    v.x *= nrm; v.y *= nrm; v.z *= nrm; v.w *= nrm;
    red_add_v4(out + (size_t)ed.y * COUT + j * 4, v);
}

// ---------------------------------------------------------------------------
// Launch
// ---------------------------------------------------------------------------
extern "C" void kernel_launch(void* const* d_in, const int* in_sizes, int n_in,
                              void* d_out, int out_size) {
    const float* x     = (const float*)d_in[0];
    const void*  edges = d_in[1];
    const float* W1    = (const float*)d_in[2];
    const float* b1    = (const float*)d_in[3];
    const float* W2    = (const float*)d_in[4];
    const float* b2    = (const float*)d_in[5];
    float* out = (float*)d_out;

    const int N = in_sizes[0] / F_IN;
    const int E = in_sizes[1] / 2;

    float *deg, *dinv, *aggx, *h2;
    int2* ebuf;
    cudaGetSymbolAddress((void**)&deg,  g_deg);
    cudaGetSymbolAddress((void**)&dinv, g_dinv);
    cudaGetSymbolAddress((void**)&ebuf, g_edges);
    cudaGetSymbolAddress((void**)&aggx, g_aggx);
    cudaGetSymbolAddress((void**)&h2,   g_h2);

    const int fused_smem = SMEM_FLOATS * 4;  // 156288 B
    cudaFuncSetAttribute(k_fused_gemm, cudaFuncAttributeMaxDynamicSharedMemorySize, fused_smem);

    k_detect_dtype<<<1, 32>>>((const int*)edges);                      // 0
    k_init_deg<<<(N + 255) / 256, 256>>>(deg, N);                      // 1
    k_conv_deg<<<(E + 255) / 256, 256>>>(edges, ebuf, deg, E);         // 2
    k_dinv<<<(N + 255) / 256, 256>>>(deg, dinv, N);                    // 3
    k_init_aggx<<<(N * 16 + 255) / 256, 256>>>(x, dinv, aggx, N);      // 4
    k_scatter_x<<<(int)(((long long)E * 16 + 255) / 256), 256>>>(      // 5 <- profiled
        ebuf, dinv, x, aggx, E);
    k_fused_gemm<<<(N + 255) / 256, 256, fused_smem>>>(                // 6
        aggx, W1, b1, W2, b2, dinv, h2, out, N);
    k_scatter2<<<(int)(((long long)E * 10 + 255) / 256), 256>>>(       // 7
        ebuf, dinv, h2, out, E);
}

// round 3
// speedup vs baseline: 2.2232x; 1.4291x over previous
#include <cuda_runtime.h>
#include <cuda_bf16.h>
#include <stdint.h>

// ---------------------------------------------------------------------------
// GCN2 via CSR (counting sort by destination) — no atomics in the hot path.
//   deg[d]   = 1 + indeg(d);  dinv = rsqrt(deg)
//   y1       = dinv * x                      (row prescale)
//   aggx[d]  = dinv[d] * (sum_{s in N(d)} y1[s] + y1[d])
//   h        = relu(aggx @ W1 + b1)
//   y2       = dinv * (h @ W2)               (fused into GEMM epilogue)
//   out[d]   = dinv[d] * (sum y2[s] + y2[d]) + b2
// Shapes: N=100000, F=64, H=128, C=40, E=1600000
// ---------------------------------------------------------------------------

#define NMAX 100032
#define EMAX 1600000
#define F_IN 64
#define HID  128
#define COUT 40

__device__ int   g_deg[NMAX];        // indegree (without self loop)
__device__ int   g_cursor[NMAX];
__device__ int   g_offsets[NMAX + 1];
__device__ int   g_partials[64];
__device__ int2  g_edges[EMAX];
__device__ int   g_sorted_src[EMAX];
__device__ float g_y1[(size_t)NMAX * F_IN];
__device__ float g_aggx[(size_t)NMAX * F_IN];
__device__ float g_y2[(size_t)NMAX * COUT];
__device__ int   g_is64;

#define SCAN_CHUNK 2048   // 256 threads x 8

// ---------------------------------------------------------------------------
// (0) dtype detect: int64 indices have all-zero odd words (values < 2^31)
// ---------------------------------------------------------------------------
__global__ void k_detect_dtype(const int* __restrict__ edge_words) {
    if (threadIdx.x == 0) {
        int all_zero = 1;
        #pragma unroll
        for (int i = 0; i < 32; i++)
            if (edge_words[2 * i + 1] != 0) all_zero = 0;
        g_is64 = all_zero;
    }
}

// (1) zero deg + cursor
__global__ void k_zero(int* __restrict__ deg, int* __restrict__ cursor, int N) {
    int i = blockIdx.x * blockDim.x + threadIdx.x;
    if (i < N) { deg[i] = 0; cursor[i] = 0; }
}

// (2) convert indices to int2 + histogram destinations
__global__ void k_conv_hist(const void* __restrict__ edges_raw, int2* __restrict__ edges,
                            int* __restrict__ deg, int E) {
    int e = blockIdx.x * blockDim.x + threadIdx.x;
    if (e >= E) return;
    int s, d;
    if (g_is64) {
        s = (int)((const long long*)edges_raw)[e];
        d = (int)((const long long*)edges_raw)[(long long)E + e];
    } else {
        s = ((const int*)edges_raw)[e];
        d = ((const int*)edges_raw)[(long long)E + e];
    }
    edges[e] = make_int2(s, d);
    atomicAdd(&deg[d], 1);
}

// (3) scan pass A: per-chunk sums
__global__ void k_scan_a(const int* __restrict__ deg, int* __restrict__ partials, int N) {
    __shared__ int sm[256];
    int b = blockIdx.x, tid = threadIdx.x;
    int base = b * SCAN_CHUNK + tid * 8;
    int s = 0;
    #pragma unroll
    for (int k = 0; k < 8; k++) {
        int i = base + k;
        if (i < N) s += deg[i];
    }
    sm[tid] = s;
    __syncthreads();
    #pragma unroll
    for (int st = 128; st > 0; st >>= 1) {
        if (tid < st) sm[tid] += sm[tid + st];
        __syncthreads();
    }
    if (tid == 0) partials[b] = sm[0];
}

// (4) scan pass B: exclusive scan of chunk sums (single thread; ~49 values)
__global__ void k_scan_b(int* __restrict__ partials, int* __restrict__ offsets,
                         int nchunks, int N) {
    if (threadIdx.x == 0) {
        int run = 0;
        for (int i = 0; i < nchunks; i++) {
            int t = partials[i];
            partials[i] = run;
            run += t;
        }
        offsets[N] = run;  // == E
    }
}

// (5) scan pass C: per-chunk exclusive scan + chunk base
__global__ void k_scan_c(const int* __restrict__ deg, const int* __restrict__ partials,
                         int* __restrict__ offsets, int N) {
    __shared__ int sm[256];
    int b = blockIdx.x, tid = threadIdx.x;
    int base = b * SCAN_CHUNK + tid * 8;
    int v[8];
    int s = 0;
    #pragma unroll
    for (int k = 0; k < 8; k++) {
        int i = base + k;
        v[k] = (i < N) ? deg[i] : 0;
        s += v[k];
    }
    sm[tid] = s;
    __syncthreads();
    // inclusive Hillis-Steele over thread sums
    #pragma unroll
    for (int st = 1; st < 256; st <<= 1) {
        int add = (tid >= st) ? sm[tid - st] : 0;
        __syncthreads();
        sm[tid] += add;
        __syncthreads();
    }
    int thr_excl = sm[tid] - s + partials[b];
    int run = thr_excl;
    #pragma unroll
    for (int k = 0; k < 8; k++) {
        int i = base + k;
        if (i < N) offsets[i] = run;
        run += v[k];
    }
}

// (6) place edges into destination segments
__global__ void k_place(const int2* __restrict__ edges, const int* __restrict__ offsets,
                        int* __restrict__ cursor, int* __restrict__ sorted_src, int E) {
    int e = blockIdx.x * blockDim.x + threadIdx.x;
    if (e >= E) return;
    int2 ed = edges[e];
    int pos = offsets[ed.y] + atomicAdd(&cursor[ed.y], 1);
    sorted_src[pos] = ed.x;
}

// (7) y1 = dinv * x
__global__ void k_y1(const float* __restrict__ x, const int* __restrict__ deg,
                     float* __restrict__ y1, int N) {
    int i = blockIdx.x * blockDim.x + threadIdx.x;  // float4 index, 16/row
    if (i >= N * 16) return;
    int n = i >> 4;
    float dv = rsqrtf((float)deg[n] + 1.0f);
    float4 v = ((const float4*)x)[i];
    v.x *= dv; v.y *= dv; v.z *= dv; v.w *= dv;
    ((float4*)y1)[i] = v;
}

// (8) agg1: aggx[d] = dinv[d] * (sum y1[s] + y1[d]); 16 lanes per dest
__global__ void k_agg1(const int* __restrict__ sorted_src, const int* __restrict__ offsets,
                       const int* __restrict__ deg, const float* __restrict__ y1,
                       float* __restrict__ aggx, int N) {
    int t = blockIdx.x * blockDim.x + threadIdx.x;
    int d = t >> 4, j = t & 15;
    if (d >= N) return;
    const float4* y4 = (const float4*)y1;
    int off = offsets[d], end = offsets[d + 1];
    float4 acc = y4[(size_t)d * 16 + j];  // self term
    int i = off;
    for (; i + 2 <= end; i += 2) {
        int s0 = sorted_src[i], s1 = sorted_src[i + 1];
        float4 a = y4[(size_t)s0 * 16 + j];
        float4 b = y4[(size_t)s1 * 16 + j];
        acc.x += a.x + b.x; acc.y += a.y + b.y;
        acc.z += a.z + b.z; acc.w += a.w + b.w;
    }
    if (i < end) {
        int s0 = sorted_src[i];
        float4 a = y4[(size_t)s0 * 16 + j];
        acc.x += a.x; acc.y += a.y; acc.z += a.z; acc.w += a.w;
    }
    float dv = rsqrtf((float)deg[d] + 1.0f);
    acc.x *= dv; acc.y *= dv; acc.z *= dv; acc.w *= dv;
    ((float4*)aggx)[(size_t)d * 16 + j] = acc;
}

// ---------------------------------------------------------------------------
// (9) fused GEMM: y2 = dinv * ( relu(aggx*W1 + b1) * W2 )
// 256-row tile, 256 threads, 4 rows/thread.
// ---------------------------------------------------------------------------
#define XS_STRIDE 68
#define HS_STRIDE 132
#define SMEM_FLOATS 39072

__global__ void __launch_bounds__(256, 1)
k_fused_gemm(const float* __restrict__ A, const float* __restrict__ W1,
             const float* __restrict__ b1, const float* __restrict__ W2,
             const int* __restrict__ deg, float* __restrict__ y2, int N) {
    extern __shared__ float sm[];
    float* xs  = sm;                     // 256 x 68
    float* ws1 = sm + 256 * XS_STRIDE;
    float* hs  = sm;                     // 256 x 132 (aliases, used after sync)
    float* w2t = sm + 256 * HS_STRIDE;

    const int tid = threadIdx.x;
    const int row0 = blockIdx.x * 256;
    const int rows = min(256, N - row0);
    const int r0 = tid >> 2, cg = tid & 3;

    {
        const float4* W4 = (const float4*)W1;
        #pragma unroll
        for (int i = tid; i < 2048; i += 256)
            *(float4*)(ws1 + (i >> 5) * 128 + (i & 31) * 4) = W4[i];
    }
    {
        const float4* A4 = (const float4*)(A + (size_t)row0 * F_IN);
        for (int i = tid; i < rows * 16; i += 256)
            *(float4*)(xs + (i >> 4) * XS_STRIDE + (i & 15) * 4) = A4[i];
        float4 z = make_float4(0.f, 0.f, 0.f, 0.f);
        for (int i = rows * 16 + tid; i < 256 * 16; i += 256)
            *(float4*)(xs + (i >> 4) * XS_STRIDE + (i & 15) * 4) = z;
    }
    __syncthreads();

    float4 acc[4][8];
    #pragma unroll
    for (int m = 0; m < 4; m++)
        #pragma unroll
        for (int j = 0; j < 8; j++) acc[m][j] = make_float4(0.f, 0.f, 0.f, 0.f);

    #pragma unroll 2
    for (int k = 0; k < 64; k++) {
        float4 w[8];
        const float* wk = ws1 + k * 128 + cg * 4;
        #pragma unroll
        for (int j = 0; j < 8; j++) w[j] = *(const float4*)(wk + j * 16);
        #pragma unroll
        for (int m = 0; m < 4; m++) {
            float a = xs[(r0 + 64 * m) * XS_STRIDE + k];
            #pragma unroll
            for (int j = 0; j < 8; j++) {
                acc[m][j].x += a * w[j].x; acc[m][j].y += a * w[j].y;
                acc[m][j].z += a * w[j].z; acc[m][j].w += a * w[j].w;
            }
        }
    }

    {
        float4 bb[8];
        #pragma unroll
        for (int j = 0; j < 8; j++) bb[j] = *(const float4*)(b1 + 16 * j + 4 * cg);
        #pragma unroll
        for (int m = 0; m < 4; m++)
            #pragma unroll
            for (int j = 0; j < 8; j++) {
                acc[m][j].x = fmaxf(acc[m][j].x + bb[j].x, 0.f);
                acc[m][j].y = fmaxf(acc[m][j].y + bb[j].y, 0.f);
                acc[m][j].z = fmaxf(acc[m][j].z + bb[j].z, 0.f);
                acc[m][j].w = fmaxf(acc[m][j].w + bb[j].w, 0.f);
            }
    }

    __syncthreads();

    #pragma unroll
    for (int m = 0; m < 4; m++)
        #pragma unroll
        for (int j = 0; j < 8; j++)
            *(float4*)(hs + (r0 + 64 * m) * HS_STRIDE + 16 * j + 4 * cg) = acc[m][j];

    for (int i = tid; i < HID * COUT; i += 256) {
        int k = i / COUT, c = i - k * COUT;
        w2t[c * HS_STRIDE + k] = W2[i];
    }
    __syncthreads();

    float acc2[4][10];
    #pragma unroll
    for (int m = 0; m < 4; m++)
        #pragma unroll
        for (int i = 0; i < 10; i++) acc2[m][i] = 0.f;

    for (int k = 0; k < 128; k += 4) {
        float4 a[4];
        #pragma unroll
        for (int m = 0; m < 4; m++)
            a[m] = *(const float4*)(hs + (r0 + 64 * m) * HS_STRIDE + k);
        #pragma unroll
        for (int i = 0; i < 10; i++) {
            float4 w = *(const float4*)(w2t + (cg * 10 + i) * HS_STRIDE + k);
            #pragma unroll
            for (int m = 0; m < 4; m++)
                acc2[m][i] += a[m].x * w.x + a[m].y * w.y + a[m].z * w.z + a[m].w * w.w;
        }
    }

    #pragma unroll
    for (int m = 0; m < 4; m++) {
        int row = row0 + r0 + 64 * m;
        if (row >= N) continue;
        float dv = rsqrtf((float)deg[row] + 1.0f);
        #pragma unroll
        for (int i = 0; i < 10; i++)
            y2[(size_t)row * COUT + cg * 10 + i] = dv * acc2[m][i];
    }
}

// (10) agg2: out[d] = dinv[d]*(sum y2[s] + y2[d]) + b2 ; 10 lanes per dest
__global__ void k_agg2(const int* __restrict__ sorted_src, const int* __restrict__ offsets,
                       const int* __restrict__ deg, const float* __restrict__ y2,
                       const float* __restrict__ b2, float* __restrict__ out, int N) {
    int t = blockIdx.x * blockDim.x + threadIdx.x;
    int d = t / 10, j = t - d * 10;
    if (d >= N) return;
    const float4* y4 = (const float4*)y2;
    int off = offsets[d], end = offsets[d + 1];
    float4 acc = y4[(size_t)d * 10 + j];  // self term
    int i = off;
    for (; i + 2 <= end; i += 2) {
        int s0 = sorted_src[i], s1 = sorted_src[i + 1];
        float4 a = y4[(size_t)s0 * 10 + j];
        float4 b = y4[(size_t)s1 * 10 + j];
        acc.x += a.x + b.x; acc.y += a.y + b.y;
        acc.z += a.z + b.z; acc.w += a.w + b.w;
    }
    if (i < end) {
        int s0 = sorted_src[i];
        float4 a = y4[(size_t)s0 * 10 + j];
        acc.x += a.x; acc.y += a.y; acc.z += a.z; acc.w += a.w;
    }
    float dv = rsqrtf((float)deg[d] + 1.0f);
    float4 bb = ((const float4*)b2)[j];
    acc.x = acc.x * dv + bb.x; acc.y = acc.y * dv + bb.y;
    acc.z = acc.z * dv + bb.z; acc.w = acc.w * dv + bb.w;
    ((float4*)out)[(size_t)d * 10 + j] = acc;
}

// ---------------------------------------------------------------------------
// Launch
// ---------------------------------------------------------------------------
extern "C" void kernel_launch(void* const* d_in, const int* in_sizes, int n_in,
                              void* d_out, int out_size) {
    const float* x     = (const float*)d_in[0];
    const void*  edges = d_in[1];
    const float* W1    = (const float*)d_in[2];
    const float* b1    = (const float*)d_in[3];
    const float* W2    = (const float*)d_in[4];
    const float* b2    = (const float*)d_in[5];
    float* out = (float*)d_out;

    const int N = in_sizes[0] / F_IN;
    const int E = in_sizes[1] / 2;
    const int nchunks = (N + SCAN_CHUNK - 1) / SCAN_CHUNK;

    int *deg, *cursor, *offsets, *partials, *ssrc;
    int2* ebuf;
    float *y1, *aggx, *y2;
    cudaGetSymbolAddress((void**)&deg,      g_deg);
    cudaGetSymbolAddress((void**)&cursor,   g_cursor);
    cudaGetSymbolAddress((void**)&offsets,  g_offsets);
    cudaGetSymbolAddress((void**)&partials, g_partials);
    cudaGetSymbolAddress((void**)&ebuf,     g_edges);
    cudaGetSymbolAddress((void**)&ssrc,     g_sorted_src);
    cudaGetSymbolAddress((void**)&y1,       g_y1);
    cudaGetSymbolAddress((void**)&aggx,     g_aggx);
    cudaGetSymbolAddress((void**)&y2,       g_y2);

    const int fused_smem = SMEM_FLOATS * 4;
    cudaFuncSetAttribute(k_fused_gemm, cudaFuncAttributeMaxDynamicSharedMemorySize, fused_smem);

    k_detect_dtype<<<1, 32>>>((const int*)edges);                            // 0
    k_zero<<<(N + 255) / 256, 256>>>(deg, cursor, N);                        // 1
    k_conv_hist<<<(E + 255) / 256, 256>>>(edges, ebuf, deg, E);              // 2
    k_scan_a<<<nchunks, 256>>>(deg, partials, N);                            // 3
    k_scan_b<<<1, 32>>>(partials, offsets, nchunks, N);                      // 4
    k_scan_c<<<nchunks, 256>>>(deg, partials, offsets, N);                   // 5
    k_place<<<(E + 255) / 256, 256>>>(ebuf, offsets, cursor, ssrc, E);       // 6
    k_y1<<<(N * 16 + 255) / 256, 256>>>(x, deg, y1, N);                      // 7
    k_agg1<<<(N * 16 + 255) / 256, 256>>>(ssrc, offsets, deg, y1, aggx, N);  // 8
    k_fused_gemm<<<(N + 255) / 256, 256, fused_smem>>>(aggx, W1, b1, W2, deg, y2, N); // 9
    k_agg2<<<(N * 10 + 255) / 256, 256>>>(ssrc, offsets, deg, y2, b2, out, N);        // 10
}

// round 4
// speedup vs baseline: 2.3100x; 1.0391x over previous
#include <cuda_runtime.h>
#include <cuda_fp16.h>
#include <stdint.h>

// ---------------------------------------------------------------------------
// GCN2 via CSR (counting sort by destination), fp16 gather operands.
//   deg[d]  = 1 + indeg(d);  dinv = rsqrt(deg)
//   y1      = half(dinv * x)
//   aggx[d] = dinv[d] * (sum_{s in N(d)} y1[s] + y1[d])      (fp32 accum)
//   h       = relu(aggx @ W1 + b1)
//   y2      = half(dinv * (h @ W2))
//   out[d]  = dinv[d] * (sum y2[s] + y2[d]) + b2             (fp32 accum)
// Shapes: N=100000, F=64, H=128, C=40, E=1600000
// ---------------------------------------------------------------------------

#define NMAX 100032
#define EMAX 1600000
#define F_IN 64
#define HID  128
#define COUT 40

__device__ int    g_deg[NMAX];
__device__ int    g_cursor[NMAX];
__device__ int    g_offsets[NMAX + 1];
__device__ int    g_partials[64];
__device__ int    g_sorted_src[EMAX];
__device__ __half g_y1[(size_t)NMAX * F_IN];    // 128B/row
__device__ float  g_aggx[(size_t)NMAX * F_IN];
__device__ __half g_y2[(size_t)NMAX * COUT];    // 80B/row
__device__ int    g_is64;

#define SCAN_CHUNK 2048

// (0) dtype detect: int64 indices have all-zero odd words (values < 2^31)
__global__ void k_detect_dtype(const int* __restrict__ edge_words) {
    if (threadIdx.x == 0) {
        int all_zero = 1;
        #pragma unroll
        for (int i = 0; i < 32; i++)
            if (edge_words[2 * i + 1] != 0) all_zero = 0;
        g_is64 = all_zero;
    }
}

// (1) zero deg + cursor
__global__ void k_zero(int* __restrict__ deg, int* __restrict__ cursor, int N) {
    int i = blockIdx.x * blockDim.x + threadIdx.x;
    if (i < N) { deg[i] = 0; cursor[i] = 0; }
}

// (2) histogram destinations (reads dst half of raw edge array only)
__global__ void k_hist(const void* __restrict__ edges_raw, int* __restrict__ deg, int E) {
    int e = blockIdx.x * blockDim.x + threadIdx.x;
    if (e >= E) return;
    int d;
    if (g_is64) d = (int)((const long long*)edges_raw)[(long long)E + e];
    else        d = ((const int*)edges_raw)[(long long)E + e];
    atomicAdd(&deg[d], 1);
}

// (3) scan pass A: per-chunk sums
__global__ void k_scan_a(const int* __restrict__ deg, int* __restrict__ partials, int N) {
    __shared__ int sm[256];
    int b = blockIdx.x, tid = threadIdx.x;
    int base = b * SCAN_CHUNK + tid * 8;
    int s = 0;
    #pragma unroll
    for (int k = 0; k < 8; k++) {
        int i = base + k;
        if (i < N) s += deg[i];
    }
    sm[tid] = s;
    __syncthreads();
    #pragma unroll
    for (int st = 128; st > 0; st >>= 1) {
        if (tid < st) sm[tid] += sm[tid + st];
        __syncthreads();
    }
    if (tid == 0) partials[b] = sm[0];
}

// (4) scan pass B: exclusive scan of chunk sums
__global__ void k_scan_b(int* __restrict__ partials, int* __restrict__ offsets,
                         int nchunks, int N) {
    if (threadIdx.x == 0) {
        int run = 0;
        for (int i = 0; i < nchunks; i++) {
            int t = partials[i];
            partials[i] = run;
            run += t;
        }
        offsets[N] = run;
    }
}

// (5) scan pass C: per-chunk exclusive scan + chunk base
__global__ void k_scan_c(const int* __restrict__ deg, const int* __restrict__ partials,
                         int* __restrict__ offsets, int N) {
    __shared__ int sm[256];
    int b = blockIdx.x, tid = threadIdx.x;
    int base = b * SCAN_CHUNK + tid * 8;
    int v[8];
    int s = 0;
    #pragma unroll
    for (int k = 0; k < 8; k++) {
        int i = base + k;
        v[k] = (i < N) ? deg[i] : 0;
        s += v[k];
    }
    sm[tid] = s;
    __syncthreads();
    #pragma unroll
    for (int st = 1; st < 256; st <<= 1) {
        int add = (tid >= st) ? sm[tid - st] : 0;
        __syncthreads();
        sm[tid] += add;
        __syncthreads();
    }
    int run = sm[tid] - s + partials[b];
    #pragma unroll
    for (int k = 0; k < 8; k++) {
        int i = base + k;
        if (i < N) offsets[i] = run;
        run += v[k];
    }
}

// (6) place edges into destination segments (reads raw src+dst)
__global__ void k_place(const void* __restrict__ edges_raw, const int* __restrict__ offsets,
                        int* __restrict__ cursor, int* __restrict__ sorted_src, int E) {
    int e = blockIdx.x * blockDim.x + threadIdx.x;
    if (e >= E) return;
    int s, d;
    if (g_is64) {
        s = (int)((const long long*)edges_raw)[e];
        d = (int)((const long long*)edges_raw)[(long long)E + e];
    } else {
        s = ((const int*)edges_raw)[e];
        d = ((const int*)edges_raw)[(long long)E + e];
    }
    int pos = offsets[d] + atomicAdd(&cursor[d], 1);
    sorted_src[pos] = s;
}

// (7) y1 = half(dinv * x); thread per float4 (= 2 half2)
__global__ void k_y1(const float* __restrict__ x, const int* __restrict__ deg,
                     __half* __restrict__ y1, int N) {
    int i = blockIdx.x * blockDim.x + threadIdx.x;
    if (i >= N * 16) return;
    int n = i >> 4;
    float dv = rsqrtf((float)deg[n] + 1.0f);
    float4 v = ((const float4*)x)[i];
    __half2 h0 = __floats2half2_rn(v.x * dv, v.y * dv);
    __half2 h1 = __floats2half2_rn(v.z * dv, v.w * dv);
    uint2 u = make_uint2(*(unsigned*)&h0, *(unsigned*)&h1);
    ((uint2*)y1)[i] = u;
}

__device__ __forceinline__ void acc8(float* acc, uint4 u) {
    float2 f;
    f = __half22float2(*(__half2*)&u.x); acc[0] += f.x; acc[1] += f.y;
    f = __half22float2(*(__half2*)&u.y); acc[2] += f.x; acc[3] += f.y;
    f = __half22float2(*(__half2*)&u.z); acc[4] += f.x; acc[5] += f.y;
    f = __half22float2(*(__half2*)&u.w); acc[6] += f.x; acc[7] += f.y;
}

// (8) agg1: 8 lanes per dest, each lane covers 8 feats (uint4 of halves)
__global__ void k_agg1(const int* __restrict__ sorted_src, const int* __restrict__ offsets,
                       const int* __restrict__ deg, const __half* __restrict__ y1,
                       float* __restrict__ aggx, int N) {
    int t = blockIdx.x * blockDim.x + threadIdx.x;
    int d = t >> 3, j = t & 7;
    if (d >= N) return;
    const uint4* y4 = (const uint4*)y1;  // 8 uint4 per row
    int off = offsets[d], end = offsets[d + 1];
    float acc[8] = {0, 0, 0, 0, 0, 0, 0, 0};
    acc8(acc, y4[(size_t)d * 8 + j]);  // self term
    int i = off;
    for (; i + 2 <= end; i += 2) {
        int s0 = sorted_src[i], s1 = sorted_src[i + 1];
        uint4 a = y4[(size_t)s0 * 8 + j];
        uint4 b = y4[(size_t)s1 * 8 + j];
        acc8(acc, a);
        acc8(acc, b);
    }
    if (i < end) acc8(acc, y4[(size_t)sorted_src[i] * 8 + j]);
    float dv = rsqrtf((float)deg[d] + 1.0f);
    float4 o0 = make_float4(acc[0] * dv, acc[1] * dv, acc[2] * dv, acc[3] * dv);
    float4 o1 = make_float4(acc[4] * dv, acc[5] * dv, acc[6] * dv, acc[7] * dv);
    float* o = aggx + (size_t)d * F_IN + j * 8;
    *(float4*)o = o0;
    *(float4*)(o + 4) = o1;
}

// ---------------------------------------------------------------------------
// (9) fused GEMM: y2 = half( dinv * ( relu(aggx*W1 + b1) * W2 ) )
// 128-row tile, 256 threads (2 rows/thread), 2 CTAs/SM.
// ---------------------------------------------------------------------------
#define XS_STRIDE 68
#define HS_STRIDE 132
// phase1: xs[128*68]=8704 | ws1[64*128]=8192  -> 16896 fl
// phase2: hs[128*132]=16896 (aliases) | w2t[40*132]=5280 -> 22176 fl = 88704 B
#define SMEM_FLOATS 22176

__global__ void __launch_bounds__(256, 2)
k_fused_gemm(const float* __restrict__ A, const float* __restrict__ W1,
             const float* __restrict__ b1, const float* __restrict__ W2,
             const int* __restrict__ deg, __half* __restrict__ y2, int N) {
    extern __shared__ float sm[];
    float* xs  = sm;                     // 128 x 68
    float* ws1 = sm + 128 * XS_STRIDE;   // 64 x 128
    float* hs  = sm;                     // 128 x 132 (aliases, after sync)
    float* w2t = sm + 128 * HS_STRIDE;   // 40 x 132

    const int tid = threadIdx.x;
    const int row0 = blockIdx.x * 128;
    const int rows = min(128, N - row0);
    const int r0 = tid >> 2, cg = tid & 3;   // r0 in [0,64)

    {
        const float4* W4 = (const float4*)W1;
        #pragma unroll
        for (int i = tid; i < 2048; i += 256)
            *(float4*)(ws1 + (i >> 5) * 128 + (i & 31) * 4) = W4[i];
    }
    {
        const float4* A4 = (const float4*)(A + (size_t)row0 * F_IN);
        for (int i = tid; i < rows * 16; i += 256)
            *(float4*)(xs + (i >> 4) * XS_STRIDE + (i & 15) * 4) = A4[i];
        float4 z = make_float4(0.f, 0.f, 0.f, 0.f);
        for (int i = rows * 16 + tid; i < 128 * 16; i += 256)
            *(float4*)(xs + (i >> 4) * XS_STRIDE + (i & 15) * 4) = z;
    }
    __syncthreads();

    // phase 1: rows r0, r0+64 ; cols {16j+4cg..+3}
    float4 acc[2][8];
    #pragma unroll
    for (int m = 0; m < 2; m++)
        #pragma unroll
        for (int j = 0; j < 8; j++) acc[m][j] = make_float4(0.f, 0.f, 0.f, 0.f);

    #pragma unroll 2
    for (int k = 0; k < 64; k++) {
        float4 w[8];
        const float* wk = ws1 + k * 128 + cg * 4;
        #pragma unroll
        for (int j = 0; j < 8; j++) w[j] = *(const float4*)(wk + j * 16);
        #pragma unroll
        for (int m = 0; m < 2; m++) {
            float a = xs[(r0 + 64 * m) * XS_STRIDE + k];
            #pragma unroll
            for (int j = 0; j < 8; j++) {
                acc[m][j].x += a * w[j].x; acc[m][j].y += a * w[j].y;
                acc[m][j].z += a * w[j].z; acc[m][j].w += a * w[j].w;
            }
        }
    }

    {
        float4 bb[8];
        #pragma unroll
        for (int j = 0; j < 8; j++) bb[j] = *(const float4*)(b1 + 16 * j + 4 * cg);
        #pragma unroll
        for (int m = 0; m < 2; m++)
            #pragma unroll
            for (int j = 0; j < 8; j++) {
                acc[m][j].x = fmaxf(acc[m][j].x + bb[j].x, 0.f);
                acc[m][j].y = fmaxf(acc[m][j].y + bb[j].y, 0.f);
                acc[m][j].z = fmaxf(acc[m][j].z + bb[j].z, 0.f);
                acc[m][j].w = fmaxf(acc[m][j].w + bb[j].w, 0.f);
            }
    }

    __syncthreads();

    #pragma unroll
    for (int m = 0; m < 2; m++)
        #pragma unroll
        for (int j = 0; j < 8; j++)
            *(float4*)(hs + (r0 + 64 * m) * HS_STRIDE + 16 * j + 4 * cg) = acc[m][j];

    for (int i = tid; i < HID * COUT; i += 256) {
        int k = i / COUT, c = i - k * COUT;
        w2t[c * HS_STRIDE + k] = W2[i];
    }
    __syncthreads();

    // phase 2: cols [cg*10, cg*10+10)
    float acc2[2][10];
    #pragma unroll
    for (int m = 0; m < 2; m++)
        #pragma unroll
        for (int i = 0; i < 10; i++) acc2[m][i] = 0.f;

    for (int k = 0; k < 128; k += 4) {
        float4 a[2];
        #pragma unroll
        for (int m = 0; m < 2; m++)
            a[m] = *(const float4*)(hs + (r0 + 64 * m) * HS_STRIDE + k);
        #pragma unroll
        for (int i = 0; i < 10; i++) {
            float4 w = *(const float4*)(w2t + (cg * 10 + i) * HS_STRIDE + k);
            #pragma unroll
            for (int m = 0; m < 2; m++)
                acc2[m][i] += a[m].x * w.x + a[m].y * w.y + a[m].z * w.z + a[m].w * w.w;
        }
    }

    #pragma unroll
    for (int m = 0; m < 2; m++) {
        int row = row0 + r0 + 64 * m;
        if (row >= N) continue;
        float dv = rsqrtf((float)deg[row] + 1.0f);
        __half2* o = (__half2*)(y2 + (size_t)row * COUT + cg * 10);
        #pragma unroll
        for (int p = 0; p < 5; p++)
            o[p] = __floats2half2_rn(acc2[m][2 * p] * dv, acc2[m][2 * p + 1] * dv);
    }
}

// (10) agg2: 5 lanes per dest, each lane covers 8 feats (uint4 of halves)
__global__ void k_agg2(const int* __restrict__ sorted_src, const int* __restrict__ offsets,
                       const int* __restrict__ deg, const __half* __restrict__ y2,
                       const float* __restrict__ b2, float* __restrict__ out, int N) {
    int t = blockIdx.x * blockDim.x + threadIdx.x;
    int d = t / 5, j = t - d * 5;
    if (d >= N) return;
    const uint4* y4 = (const uint4*)y2;  // 5 uint4 per row
    int off = offsets[d], end = offsets[d + 1];
    float acc[8] = {0, 0, 0, 0, 0, 0, 0, 0};
    acc8(acc, y4[(size_t)d * 5 + j]);  // self term
    int i = off;
    for (; i + 2 <= end; i += 2) {
        int s0 = sorted_src[i], s1 = sorted_src[i + 1];
        uint4 a = y4[(size_t)s0 * 5 + j];
        uint4 b = y4[(size_t)s1 * 5 + j];
        acc8(acc, a);
        acc8(acc, b);
    }
    if (i < end) acc8(acc, y4[(size_t)sorted_src[i] * 5 + j]);
    float dv = rsqrtf((float)deg[d] + 1.0f);
    const float* bb = b2 + j * 8;
    float* o = out + (size_t)d * COUT + j * 8;
    float4 o0 = make_float4(acc[0] * dv + bb[0], acc[1] * dv + bb[1],
                            acc[2] * dv + bb[2], acc[3] * dv + bb[3]);
    float4 o1 = make_float4(acc[4] * dv + bb[4], acc[5] * dv + bb[5],
                            acc[6] * dv + bb[6], acc[7] * dv + bb[7]);
    *(float4*)o = o0;
    *(float4*)(o + 4) = o1;
}

// ---------------------------------------------------------------------------
// Launch
// ---------------------------------------------------------------------------
extern "C" void kernel_launch(void* const* d_in, const int* in_sizes, int n_in,
                              void* d_out, int out_size) {
    const float* x     = (const float*)d_in[0];
    const void*  edges = d_in[1];
    const float* W1    = (const float*)d_in[2];
    const float* b1    = (const float*)d_in[3];
    const float* W2    = (const float*)d_in[4];
    const float* b2    = (const float*)d_in[5];
    float* out = (float*)d_out;

    const int N = in_sizes[0] / F_IN;
    const int E = in_sizes[1] / 2;
    const int nchunks = (N + SCAN_CHUNK - 1) / SCAN_CHUNK;

    int *deg, *cursor, *offsets, *partials, *ssrc;
    __half *y1, *y2;
    float *aggx;
    cudaGetSymbolAddress((void**)&deg,      g_deg);
    cudaGetSymbolAddress((void**)&cursor,   g_cursor);
    cudaGetSymbolAddress((void**)&offsets,  g_offsets);
    cudaGetSymbolAddress((void**)&partials, g_partials);
    cudaGetSymbolAddress((void**)&ssrc,     g_sorted_src);
    cudaGetSymbolAddress((void**)&y1,       g_y1);
    cudaGetSymbolAddress((void**)&aggx,     g_aggx);
    cudaGetSymbolAddress((void**)&y2,       g_y2);

    const int fused_smem = SMEM_FLOATS * 4;  // 88704 B
    cudaFuncSetAttribute(k_fused_gemm, cudaFuncAttributeMaxDynamicSharedMemorySize, fused_smem);

    k_detect_dtype<<<1, 32>>>((const int*)edges);                            // 0
    k_zero<<<(N + 255) / 256, 256>>>(deg, cursor, N);                        // 1
    k_hist<<<(E + 255) / 256, 256>>>(edges, deg, E);                         // 2
    k_scan_a<<<nchunks, 256>>>(deg, partials, N);                            // 3
    k_scan_b<<<1, 32>>>(partials, offsets, nchunks, N);                      // 4
    k_scan_c<<<nchunks, 256>>>(deg, partials, offsets, N);                   // 5
    k_place<<<(E + 255) / 256, 256>>>(edges, offsets, cursor, ssrc, E);      // 6
    k_y1<<<(N * 16 + 255) / 256, 256>>>(x, deg, y1, N);                      // 7
    k_agg1<<<(N * 8 + 255) / 256, 256>>>(ssrc, offsets, deg, y1, aggx, N);   // 8
    k_fused_gemm<<<(N + 127) / 128, 256, fused_smem>>>(aggx, W1, b1, W2, deg, y2, N); // 9
    k_agg2<<<(N * 5 + 255) / 256, 256>>>(ssrc, offsets, deg, y2, b2, out, N);         // 10
}

// round 6
// speedup vs baseline: 3.3297x; 1.4414x over previous
#include <cuda_runtime.h>
#include <cuda_fp16.h>
#include <stdint.h>

// ---------------------------------------------------------------------------
// GCN2 via CSR + mma.sync TF32 tensor-core GEMM (sm_103-safe, no tcgen05).
//   deg[d]  = 1 + indeg(d);  dinv = rsqrt(deg)
//   y1      = half(dinv * x)
//   aggx[d] = dinv[d] * (sum y1[s] + y1[d])       (fp32)
//   h       = relu(aggx @ W1 + b1)                (TF32 mma, fp32 acc)
//   y2      = half(dinv * (h @ W2))               (TF32 mma)
//   out[d]  = dinv[d] * (sum y2[s] + y2[d]) + b2
// Shapes: N=100000, F=64, H=128, C=40, E=1600000
// ---------------------------------------------------------------------------

#define NMAX 100096          // >= 782*128
#define EMAX 1600000
#define F_IN 64
#define HID  128
#define COUT 40

__device__ int    g_deg[NMAX];
__device__ int    g_cursor[NMAX];
__device__ int    g_offsets[NMAX + 1];
__device__ int    g_partials[64];
__device__ int    g_sorted_src[EMAX];
__device__ __half g_y1[(size_t)NMAX * F_IN];
__device__ float  g_aggx[(size_t)NMAX * F_IN];
__device__ __half g_y2[(size_t)NMAX * COUT];
__device__ int    g_is64;

#define SCAN_CHUNK 2048

// ============================ small helpers ================================
__device__ __forceinline__ float tf32r(float v) {
    uint32_t o;
    asm("cvt.rna.tf32.f32 %0, %1;" : "=r"(o) : "f"(v));
    return __uint_as_float(o);
}

__device__ __forceinline__ void mma_tf32(float* c, const uint32_t* a,
                                         uint32_t b0, uint32_t b1) {
    asm volatile(
        "mma.sync.aligned.m16n8k8.row.col.f32.tf32.tf32.f32 "
        "{%0,%1,%2,%3}, {%4,%5,%6,%7}, {%8,%9}, {%0,%1,%2,%3};"
        : "+f"(c[0]), "+f"(c[1]), "+f"(c[2]), "+f"(c[3])
        : "r"(a[0]), "r"(a[1]), "r"(a[2]), "r"(a[3]), "r"(b0), "r"(b1));
}

// ============================ prep kernels =================================
__global__ void k_detect_dtype(const int* __restrict__ edge_words) {
    if (threadIdx.x == 0) {
        int all_zero = 1;
        #pragma unroll
        for (int i = 0; i < 32; i++)
            if (edge_words[2 * i + 1] != 0) all_zero = 0;
        g_is64 = all_zero;
    }
}

__global__ void k_zero(int* __restrict__ deg, int* __restrict__ cursor, int N) {
    int i = blockIdx.x * blockDim.x + threadIdx.x;
    if (i < N) { deg[i] = 0; cursor[i] = 0; }
}

__global__ void k_hist(const void* __restrict__ edges_raw, int* __restrict__ deg, int E) {
    int e = blockIdx.x * blockDim.x + threadIdx.x;
    if (e >= E) return;
    int d;
    if (g_is64) d = (int)((const long long*)edges_raw)[(long long)E + e];
    else        d = ((const int*)edges_raw)[(long long)E + e];
    atomicAdd(&deg[d], 1);
}

__global__ void k_scan_a(const int* __restrict__ deg, int* __restrict__ partials, int N) {
    __shared__ int sm[256];
    int b = blockIdx.x, tid = threadIdx.x;
    int base = b * SCAN_CHUNK + tid * 8;
    int s = 0;
    #pragma unroll
    for (int k = 0; k < 8; k++) {
        int i = base + k;
        if (i < N) s += deg[i];
    }
    sm[tid] = s;
    __syncthreads();
    #pragma unroll
    for (int st = 128; st > 0; st >>= 1) {
        if (tid < st) sm[tid] += sm[tid + st];
        __syncthreads();
    }
    if (tid == 0) partials[b] = sm[0];
}

__global__ void k_scan_b(int* __restrict__ partials, int* __restrict__ offsets,
                         int nchunks, int N) {
    if (threadIdx.x == 0) {
        int run = 0;
        for (int i = 0; i < nchunks; i++) {
            int t = partials[i];
            partials[i] = run;
            run += t;
        }
        offsets[N] = run;
    }
}

__global__ void k_scan_c(const int* __restrict__ deg, const int* __restrict__ partials,
                         int* __restrict__ offsets, int N) {
    __shared__ int sm[256];
    int b = blockIdx.x, tid = threadIdx.x;
    int base = b * SCAN_CHUNK + tid * 8;
    int v[8];
    int s = 0;
    #pragma unroll
    for (int k = 0; k < 8; k++) {
        int i = base + k;
        v[k] = (i < N) ? deg[i] : 0;
        s += v[k];
    }
    sm[tid] = s;
    __syncthreads();
    #pragma unroll
    for (int st = 1; st < 256; st <<= 1) {
        int add = (tid >= st) ? sm[tid - st] : 0;
        __syncthreads();
        sm[tid] += add;
        __syncthreads();
    }
    int run = sm[tid] - s + partials[b];
    #pragma unroll
    for (int k = 0; k < 8; k++) {
        int i = base + k;
        if (i < N) offsets[i] = run;
        run += v[k];
    }
}

__global__ void k_place(const void* __restrict__ edges_raw, const int* __restrict__ offsets,
                        int* __restrict__ cursor, int* __restrict__ sorted_src, int E) {
    int e = blockIdx.x * blockDim.x + threadIdx.x;
    if (e >= E) return;
    int s, d;
    if (g_is64) {
        s = (int)((const long long*)edges_raw)[e];
        d = (int)((const long long*)edges_raw)[(long long)E + e];
    } else {
        s = ((const int*)edges_raw)[e];
        d = ((const int*)edges_raw)[(long long)E + e];
    }
    int pos = offsets[d] + atomicAdd(&cursor[d], 1);
    sorted_src[pos] = s;
}

__global__ void k_y1(const float* __restrict__ x, const int* __restrict__ deg,
                     __half* __restrict__ y1, int N) {
    int i = blockIdx.x * blockDim.x + threadIdx.x;
    if (i >= N * 16) return;
    int n = i >> 4;
    float dv = rsqrtf((float)deg[n] + 1.0f);
    float4 v = ((const float4*)x)[i];
    __half2 h0 = __floats2half2_rn(v.x * dv, v.y * dv);
    __half2 h1 = __floats2half2_rn(v.z * dv, v.w * dv);
    uint2 u = make_uint2(*(unsigned*)&h0, *(unsigned*)&h1);
    ((uint2*)y1)[i] = u;
}

__device__ __forceinline__ void acc8(float* acc, uint4 u) {
    float2 f;
    f = __half22float2(*(__half2*)&u.x); acc[0] += f.x; acc[1] += f.y;
    f = __half22float2(*(__half2*)&u.y); acc[2] += f.x; acc[3] += f.y;
    f = __half22float2(*(__half2*)&u.z); acc[4] += f.x; acc[5] += f.y;
    f = __half22float2(*(__half2*)&u.w); acc[6] += f.x; acc[7] += f.y;
}

// agg1: 8 lanes per dest; fp16 gathers, fp32 accumulate/output
__global__ void k_agg1(const int* __restrict__ sorted_src, const int* __restrict__ offsets,
                       const int* __restrict__ deg, const __half* __restrict__ y1,
                       float* __restrict__ aggx, int N) {
    int t = blockIdx.x * blockDim.x + threadIdx.x;
    int d = t >> 3, j = t & 7;
    if (d >= N) return;
    const uint4* y4 = (const uint4*)y1;
    int off = offsets[d], end = offsets[d + 1];
    float acc[8] = {0, 0, 0, 0, 0, 0, 0, 0};
    acc8(acc, y4[(size_t)d * 8 + j]);
    int i = off;
    for (; i + 2 <= end; i += 2) {
        int s0 = sorted_src[i], s1 = sorted_src[i + 1];
        uint4 a = y4[(size_t)s0 * 8 + j];
        uint4 b = y4[(size_t)s1 * 8 + j];
        acc8(acc, a);
        acc8(acc, b);
    }
    if (i < end) acc8(acc, y4[(size_t)sorted_src[i] * 8 + j]);
    float dv = rsqrtf((float)deg[d] + 1.0f);
    float* o = aggx + (size_t)d * F_IN + j * 8;
    *(float4*)o       = make_float4(acc[0] * dv, acc[1] * dv, acc[2] * dv, acc[3] * dv);
    *(float4*)(o + 4) = make_float4(acc[4] * dv, acc[5] * dv, acc[6] * dv, acc[7] * dv);
}

// ======================= fused TF32 tensor-core GEMM =======================
// CTA = 128 rows, 256 threads (8 warps).
// Layer1: C1[128x128] = A[128x64] @ W1 ; warp tile 32x64 (w&3 -> m, w>>2 -> n half)
// Layer2: C2[128x64]  = h[128x128] @ W2pad ; warp tile 32x32
// SMEM (floats): xs 128x68 @0 | bs1 64x136 @8704 | hs 128x132 @0 (alias) | bs2 128x72 @17408
#define XS_STR  68
#define BS1_STR 136
#define HS_STR  132
#define BS2_STR 72
#define GEMM_SMEM ((17408 + 9216) * 4)   // 106496 B

__global__ void __launch_bounds__(256, 2)
k_gemm(const float* __restrict__ aggx, const float* __restrict__ W1,
       const float* __restrict__ b1, const float* __restrict__ W2,
       const int* __restrict__ deg, __half* __restrict__ y2, int N) {
    extern __shared__ float sm[];
    float* xs  = sm;            // 128 x 68
    float* bs1 = sm + 8704;     // 64 x 136
    float* hs  = sm;            // 128 x 132 (aliases xs+bs1 after sync)
    float* bs2 = sm + 17408;    // 128 x 72

    const int tid = threadIdx.x;
    const int lane = tid & 31, w = tid >> 5;
    const int g = lane >> 2, t = lane & 3;
    const int row0 = blockIdx.x * 128;

    // ---- load W1 [k<64][n<128] (tf32-rounded) ----
    for (int i = tid; i < 64 * 128; i += 256) {
        int k = i >> 7, n = i & 127;
        bs1[k * BS1_STR + n] = tf32r(__ldg(W1 + i));
    }
    // ---- load W2 [k<128][n<72], pad n>=40 with 0 ----
    for (int i = tid; i < 128 * 72; i += 256) {
        int k = i / 72, n = i - k * 72;
        bs2[k * BS2_STR + n] = (n < COUT) ? tf32r(__ldg(W2 + k * COUT + n)) : 0.f;
    }
    // ---- load A tile (tf32-rounded) ----
    {
        const float4* A4 = (const float4*)(aggx + (size_t)row0 * F_IN);
        for (int i = tid; i < 128 * 16; i += 256) {
            float4 v = A4[i];
            float* p = xs + (i >> 4) * XS_STR + (i & 15) * 4;
            p[0] = tf32r(v.x); p[1] = tf32r(v.y);
            p[2] = tf32r(v.z); p[3] = tf32r(v.w);
        }
    }
    __syncthreads();

    // ================= layer 1: warp tile 32 x 64, K = 64 =================
    const int m0 = (w & 3) * 32;
    const int n1 = (w >> 2) * 64;

    float c1[2][8][4];
    #pragma unroll
    for (int mf = 0; mf < 2; mf++)
        #pragma unroll
        for (int nf = 0; nf < 8; nf++)
            #pragma unroll
            for (int i = 0; i < 4; i++) c1[mf][nf][i] = 0.f;

    #pragma unroll
    for (int ks = 0; ks < 8; ks++) {
        int k8 = ks * 8;
        uint32_t a[2][4];
        #pragma unroll
        for (int mf = 0; mf < 2; mf++) {
            const float* p = xs + (m0 + mf * 16 + g) * XS_STR + k8 + t;
            a[mf][0] = __float_as_uint(p[0]);
            a[mf][1] = __float_as_uint(p[8 * XS_STR]);
            a[mf][2] = __float_as_uint(p[4]);
            a[mf][3] = __float_as_uint(p[8 * XS_STR + 4]);
        }
        #pragma unroll
        for (int nf = 0; nf < 8; nf++) {
            const float* bp = bs1 + (k8 + t) * BS1_STR + n1 + nf * 8 + g;
            uint32_t b0 = __float_as_uint(bp[0]);
            uint32_t b1v = __float_as_uint(bp[4 * BS1_STR]);
            mma_tf32(c1[0][nf], a[0], b0, b1v);
            mma_tf32(c1[1][nf], a[1], b0, b1v);
        }
    }
    __syncthreads();   // xs/bs1 reads complete; hs may alias them now

    // ---- epilogue 1: h = tf32(relu(c1 + b1)) -> hs ----
    #pragma unroll
    for (int mf = 0; mf < 2; mf++) {
        int rb = m0 + mf * 16 + g;
        #pragma unroll
        for (int nf = 0; nf < 8; nf++) {
            int cb = n1 + nf * 8 + 2 * t;
            float bb0 = __ldg(b1 + cb), bb1 = __ldg(b1 + cb + 1);
            hs[rb * HS_STR + cb]           = tf32r(fmaxf(c1[mf][nf][0] + bb0, 0.f));
            hs[rb * HS_STR + cb + 1]       = tf32r(fmaxf(c1[mf][nf][1] + bb1, 0.f));
            hs[(rb + 8) * HS_STR + cb]     = tf32r(fmaxf(c1[mf][nf][2] + bb0, 0.f));
            hs[(rb + 8) * HS_STR + cb + 1] = tf32r(fmaxf(c1[mf][nf][3] + bb1, 0.f));
        }
    }
    __syncthreads();

    // ================= layer 2: warp tile 32 x 32, K = 128 =================
    const int n2 = (w >> 2) * 32;   // 0 or 32; cols >= 40 are zero-padded

    float c2[2][4][4];
    #pragma unroll
    for (int mf = 0; mf < 2; mf++)
        #pragma unroll
        for (int nf = 0; nf < 4; nf++)
            #pragma unroll
            for (int i = 0; i < 4; i++) c2[mf][nf][i] = 0.f;

    #pragma unroll 4
    for (int ks = 0; ks < 16; ks++) {
        int k8 = ks * 8;
        uint32_t a[2][4];
        #pragma unroll
        for (int mf = 0; mf < 2; mf++) {
            const float* p = hs + (m0 + mf * 16 + g) * HS_STR + k8 + t;
            a[mf][0] = __float_as_uint(p[0]);
            a[mf][1] = __float_as_uint(p[8 * HS_STR]);
            a[mf][2] = __float_as_uint(p[4]);
            a[mf][3] = __float_as_uint(p[8 * HS_STR + 4]);
        }
        #pragma unroll
        for (int nf = 0; nf < 4; nf++) {
            if (n2 + nf * 8 < COUT) {   // skip all-zero fragments (n2=32, nf>=1)
                const float* bp = bs2 + (k8 + t) * BS2_STR + n2 + nf * 8 + g;
                uint32_t b0 = __float_as_uint(bp[0]);
                uint32_t b1v = __float_as_uint(bp[4 * BS2_STR]);
                mma_tf32(c2[0][nf], a[0], b0, b1v);
                mma_tf32(c2[1][nf], a[1], b0, b1v);
            }
        }
    }

    // ---- epilogue 2: y2 = half(dinv * c2) ----
    #pragma unroll
    for (int mf = 0; mf < 2; mf++) {
        int r0g = row0 + m0 + mf * 16 + g;
        int r1g = r0g + 8;
        float dv0 = 0.f, dv1 = 0.f;
        if (r0g < N) dv0 = rsqrtf((float)deg[r0g] + 1.0f);
        if (r1g < N) dv1 = rsqrtf((float)deg[r1g] + 1.0f);
        #pragma unroll
        for (int nf = 0; nf < 4; nf++) {
            int cb = n2 + nf * 8 + 2 * t;
            if (cb < COUT) {
                if (r0g < N) {
                    __half2 h = __floats2half2_rn(c2[mf][nf][0] * dv0, c2[mf][nf][1] * dv0);
                    *(__half2*)(y2 + (size_t)r0g * COUT + cb) = h;
                }
                if (r1g < N) {
                    __half2 h = __floats2half2_rn(c2[mf][nf][2] * dv1, c2[mf][nf][3] * dv1);
                    *(__half2*)(y2 + (size_t)r1g * COUT + cb) = h;
                }
            }
        }
    }
}

// agg2: 5 lanes per dest, fp16 gathers, fp32 accum
__global__ void k_agg2(const int* __restrict__ sorted_src, const int* __restrict__ offsets,
                       const int* __restrict__ deg, const __half* __restrict__ y2,
                       const float* __restrict__ b2, float* __restrict__ out, int N) {
    int t = blockIdx.x * blockDim.x + threadIdx.x;
    int d = t / 5, j = t - d * 5;
    if (d >= N) return;
    const uint4* y4 = (const uint4*)y2;
    int off = offsets[d], end = offsets[d + 1];
    float acc[8] = {0, 0, 0, 0, 0, 0, 0, 0};
    acc8(acc, y4[(size_t)d * 5 + j]);
    int i = off;
    for (; i + 2 <= end; i += 2) {
        int s0 = sorted_src[i], s1 = sorted_src[i + 1];
        uint4 a = y4[(size_t)s0 * 5 + j];
        uint4 b = y4[(size_t)s1 * 5 + j];
        acc8(acc, a);
        acc8(acc, b);
    }
    if (i < end) acc8(acc, y4[(size_t)sorted_src[i] * 5 + j]);
    float dv = rsqrtf((float)deg[d] + 1.0f);
    const float* bb = b2 + j * 8;
    float* o = out + (size_t)d * COUT + j * 8;
    *(float4*)o       = make_float4(acc[0] * dv + bb[0], acc[1] * dv + bb[1],
                                    acc[2] * dv + bb[2], acc[3] * dv + bb[3]);
    *(float4*)(o + 4) = make_float4(acc[4] * dv + bb[4], acc[5] * dv + bb[5],
                                    acc[6] * dv + bb[6], acc[7] * dv + bb[7]);
}

// ================================ launch ===================================
extern "C" void kernel_launch(void* const* d_in, const int* in_sizes, int n_in,
                              void* d_out, int out_size) {
    const float* x     = (const float*)d_in[0];
    const void*  edges = d_in[1];
    const float* W1    = (const float*)d_in[2];
    const float* b1    = (const float*)d_in[3];
    const float* W2    = (const float*)d_in[4];
    const float* b2    = (const float*)d_in[5];
    float* out = (float*)d_out;

    const int N = in_sizes[0] / F_IN;
    const int E = in_sizes[1] / 2;
    const int nchunks = (N + SCAN_CHUNK - 1) / SCAN_CHUNK;

    int *deg, *cursor, *offsets, *partials, *ssrc;
    __half *y1, *y2;
    float *aggx;
    cudaGetSymbolAddress((void**)&deg,      g_deg);
    cudaGetSymbolAddress((void**)&cursor,   g_cursor);
    cudaGetSymbolAddress((void**)&offsets,  g_offsets);
    cudaGetSymbolAddress((void**)&partials, g_partials);
    cudaGetSymbolAddress((void**)&ssrc,     g_sorted_src);
    cudaGetSymbolAddress((void**)&y1,       g_y1);
    cudaGetSymbolAddress((void**)&aggx,     g_aggx);
    cudaGetSymbolAddress((void**)&y2,       g_y2);

    cudaFuncSetAttribute(k_gemm, cudaFuncAttributeMaxDynamicSharedMemorySize, GEMM_SMEM);

    k_detect_dtype<<<1, 32>>>((const int*)edges);                            // 0
    k_zero<<<(N + 255) / 256, 256>>>(deg, cursor, N);                        // 1
    k_hist<<<(E + 255) / 256, 256>>>(edges, deg, E);                         // 2
    k_scan_a<<<nchunks, 256>>>(deg, partials, N);                            // 3
    k_scan_b<<<1, 32>>>(partials, offsets, nchunks, N);                      // 4
    k_scan_c<<<nchunks, 256>>>(deg, partials, offsets, N);                   // 5
    k_place<<<(E + 255) / 256, 256>>>(edges, offsets, cursor, ssrc, E);      // 6
    k_y1<<<(N * 16 + 255) / 256, 256>>>(x, deg, y1, N);                      // 7
    k_agg1<<<(N * 8 + 255) / 256, 256>>>(ssrc, offsets, deg, y1, aggx, N);   // 8
    k_gemm<<<(N + 127) / 128, 256, GEMM_SMEM>>>(aggx, W1, b1, W2, deg, y2, N); // 9
    k_agg2<<<(N * 5 + 255) / 256, 256>>>(ssrc, offsets, deg, y2, b2, out, N);  // 10
}

// round 7
// speedup vs baseline: 3.3871x; 1.0172x over previous
#include <cuda_runtime.h>
#include <cuda_fp16.h>
#include <stdint.h>

// ---------------------------------------------------------------------------
// GCN2 via CSR + mma.sync TF32 tensor-core GEMM (sm_103-safe).
//   deg[d]  = 1 + indeg(d);  dinv = rsqrt(deg)
//   y1      = half(dinv * x)
//   aggx[d] = dinv[d] * (sum y1[s] + y1[d])       (fp32, MLP-4 gather loop)
//   h       = relu(aggx @ W1 + b1)                (TF32 mma, fp32 acc)
//   y2      = half(dinv * (h @ W2))               (TF32 mma)
//   out[d]  = dinv[d] * (sum y2[s] + y2[d]) + b2  (MLP-4 gather loop)
// Shapes: N=100000, F=64, H=128, C=40, E=1600000
// ---------------------------------------------------------------------------

#define NMAX 100096
#define EMAX 1600000
#define F_IN 64
#define HID  128
#define COUT 40

__device__ int    g_deg[NMAX];
__device__ int    g_cursor[NMAX];
__device__ int    g_offsets[NMAX + 1];
__device__ int    g_partials[64];
__device__ int    g_sorted_src[EMAX];
__device__ __half g_y1[(size_t)NMAX * F_IN];
__device__ float  g_aggx[(size_t)NMAX * F_IN];
__device__ __half g_y2[(size_t)NMAX * COUT];
__device__ int    g_is64;

#define SCAN_CHUNK 2048

// ============================ small helpers ================================
__device__ __forceinline__ float tf32r(float v) {
    uint32_t o;
    asm("cvt.rna.tf32.f32 %0, %1;" : "=r"(o) : "f"(v));
    return __uint_as_float(o);
}

__device__ __forceinline__ void mma_tf32(float* c, const uint32_t* a,
                                         uint32_t b0, uint32_t b1) {
    asm volatile(
        "mma.sync.aligned.m16n8k8.row.col.f32.tf32.tf32.f32 "
        "{%0,%1,%2,%3}, {%4,%5,%6,%7}, {%8,%9}, {%0,%1,%2,%3};"
        : "+f"(c[0]), "+f"(c[1]), "+f"(c[2]), "+f"(c[3])
        : "r"(a[0]), "r"(a[1]), "r"(a[2]), "r"(a[3]), "r"(b0), "r"(b1));
}

__device__ __forceinline__ void acc8(float* acc, uint4 u) {
    float2 f;
    f = __half22float2(*(__half2*)&u.x); acc[0] += f.x; acc[1] += f.y;
    f = __half22float2(*(__half2*)&u.y); acc[2] += f.x; acc[3] += f.y;
    f = __half22float2(*(__half2*)&u.z); acc[4] += f.x; acc[5] += f.y;
    f = __half22float2(*(__half2*)&u.w); acc[6] += f.x; acc[7] += f.y;
}

// ============================ prep kernels =================================
// (1) zero deg + cursor ; block 0 also detects index dtype
__global__ void k_zero(int* __restrict__ deg, int* __restrict__ cursor,
                       const int* __restrict__ edge_words, int N) {
    int i = blockIdx.x * blockDim.x + threadIdx.x;
    if (i < N) { deg[i] = 0; cursor[i] = 0; }
    if (blockIdx.x == 0 && threadIdx.x == 0) {
        int all_zero = 1;
        #pragma unroll
        for (int k = 0; k < 32; k++)
            if (edge_words[2 * k + 1] != 0) all_zero = 0;
        g_is64 = all_zero;
    }
}

__global__ void k_hist(const void* __restrict__ edges_raw, int* __restrict__ deg, int E) {
    int e = blockIdx.x * blockDim.x + threadIdx.x;
    if (e >= E) return;
    int d;
    if (g_is64) d = (int)((const long long*)edges_raw)[(long long)E + e];
    else        d = ((const int*)edges_raw)[(long long)E + e];
    atomicAdd(&deg[d], 1);
}

__global__ void k_scan_a(const int* __restrict__ deg, int* __restrict__ partials, int N) {
    __shared__ int sm[256];
    int b = blockIdx.x, tid = threadIdx.x;
    int base = b * SCAN_CHUNK + tid * 8;
    int s = 0;
    #pragma unroll
    for (int k = 0; k < 8; k++) {
        int i = base + k;
        if (i < N) s += deg[i];
    }
    sm[tid] = s;
    __syncthreads();
    #pragma unroll
    for (int st = 128; st > 0; st >>= 1) {
        if (tid < st) sm[tid] += sm[tid + st];
        __syncthreads();
    }
    if (tid == 0) partials[b] = sm[0];
}

// scan_c: per-chunk exclusive scan; each block derives its own base from
// the chunk partials (<= 64 of them, L2-hot). Last block writes offsets[N].
__global__ void k_scan_c(const int* __restrict__ deg, const int* __restrict__ partials,
                         int* __restrict__ offsets, int nchunks, int N) {
    __shared__ int sm[256];
    __shared__ int sbase;
    int b = blockIdx.x, tid = threadIdx.x;

    // base = sum partials[0..b-1] ; warp 0 handles (nchunks <= 64)
    if (tid < 64) {
        int v = (tid < b) ? partials[tid] : 0;
        #pragma unroll
        for (int st = 16; st > 0; st >>= 1)
            v += __shfl_down_sync(0xffffffff, v, st);
        v += __shfl_sync(0xffffffff, v, 0);  // placeholder keep lanes in sync
        if (tid == 0) sbase = 0;             // init
    }
    __syncthreads();
    if (tid < 64) {
        int v = (tid < b) ? partials[tid] : 0;
        atomicAdd(&sbase, v);
    }

    int base = b * SCAN_CHUNK + tid * 8;
    int v[8];
    int s = 0;
    #pragma unroll
    for (int k = 0; k < 8; k++) {
        int i = base + k;
        v[k] = (i < N) ? deg[i] : 0;
        s += v[k];
    }
    sm[tid] = s;
    __syncthreads();
    #pragma unroll
    for (int st = 1; st < 256; st <<= 1) {
        int add = (tid >= st) ? sm[tid - st] : 0;
        __syncthreads();
        sm[tid] += add;
        __syncthreads();
    }
    int run = sm[tid] - s + sbase;
    #pragma unroll
    for (int k = 0; k < 8; k++) {
        int i = base + k;
        if (i < N) offsets[i] = run;
        run += v[k];
    }
    if (b == nchunks - 1 && tid == 255) offsets[N] = sm[255] + sbase;
}

__global__ void k_place(const void* __restrict__ edges_raw, const int* __restrict__ offsets,
                        int* __restrict__ cursor, int* __restrict__ sorted_src, int E) {
    int e = blockIdx.x * blockDim.x + threadIdx.x;
    if (e >= E) return;
    int s, d;
    if (g_is64) {
        s = (int)((const long long*)edges_raw)[e];
        d = (int)((const long long*)edges_raw)[(long long)E + e];
    } else {
        s = ((const int*)edges_raw)[e];
        d = ((const int*)edges_raw)[(long long)E + e];
    }
    int pos = offsets[d] + atomicAdd(&cursor[d], 1);
    sorted_src[pos] = s;
}

__global__ void k_y1(const float* __restrict__ x, const int* __restrict__ deg,
                     __half* __restrict__ y1, int N) {
    int i = blockIdx.x * blockDim.x + threadIdx.x;
    if (i >= N * 16) return;
    int n = i >> 4;
    float dv = rsqrtf((float)deg[n] + 1.0f);
    float4 v = ((const float4*)x)[i];
    __half2 h0 = __floats2half2_rn(v.x * dv, v.y * dv);
    __half2 h1 = __floats2half2_rn(v.z * dv, v.w * dv);
    uint2 u = make_uint2(*(unsigned*)&h0, *(unsigned*)&h1);
    ((uint2*)y1)[i] = u;
}

// ===================== aggregation (MLP-4 gather loops) ====================
// agg1: 8 lanes per dest; fp16 gathers, fp32 accumulate/output
__global__ void k_agg1(const int* __restrict__ sorted_src, const int* __restrict__ offsets,
                       const int* __restrict__ deg, const __half* __restrict__ y1,
                       float* __restrict__ aggx, int N) {
    int t = blockIdx.x * blockDim.x + threadIdx.x;
    int d = t >> 3, j = t & 7;
    if (d >= N) return;
    const uint4* y4 = (const uint4*)y1;
    int off = offsets[d], end = offsets[d + 1];
    float acc[8] = {0, 0, 0, 0, 0, 0, 0, 0};
    acc8(acc, y4[(size_t)d * 8 + j]);  // self term
    int i = off;
    for (; i + 4 <= end; i += 4) {
        int s0 = __ldg(sorted_src + i);
        int s1 = __ldg(sorted_src + i + 1);
        int s2 = __ldg(sorted_src + i + 2);
        int s3 = __ldg(sorted_src + i + 3);
        uint4 a = y4[(size_t)s0 * 8 + j];
        uint4 b = y4[(size_t)s1 * 8 + j];
        uint4 c = y4[(size_t)s2 * 8 + j];
        uint4 e = y4[(size_t)s3 * 8 + j];
        acc8(acc, a); acc8(acc, b); acc8(acc, c); acc8(acc, e);
    }
    if (i + 2 <= end) {
        int s0 = __ldg(sorted_src + i);
        int s1 = __ldg(sorted_src + i + 1);
        uint4 a = y4[(size_t)s0 * 8 + j];
        uint4 b = y4[(size_t)s1 * 8 + j];
        acc8(acc, a); acc8(acc, b);
        i += 2;
    }
    if (i < end) acc8(acc, y4[(size_t)__ldg(sorted_src + i) * 8 + j]);
    float dv = rsqrtf((float)deg[d] + 1.0f);
    float* o = aggx + (size_t)d * F_IN + j * 8;
    *(float4*)o       = make_float4(acc[0] * dv, acc[1] * dv, acc[2] * dv, acc[3] * dv);
    *(float4*)(o + 4) = make_float4(acc[4] * dv, acc[5] * dv, acc[6] * dv, acc[7] * dv);
}

// agg2: 5 lanes per dest; fp16 gathers, fp32 accum, writes final out
__global__ void k_agg2(const int* __restrict__ sorted_src, const int* __restrict__ offsets,
                       const int* __restrict__ deg, const __half* __restrict__ y2,
                       const float* __restrict__ b2, float* __restrict__ out, int N) {
    int t = blockIdx.x * blockDim.x + threadIdx.x;
    int d = t / 5, j = t - d * 5;
    if (d >= N) return;
    const uint4* y4 = (const uint4*)y2;
    int off = offsets[d], end = offsets[d + 1];
    float acc[8] = {0, 0, 0, 0, 0, 0, 0, 0};
    acc8(acc, y4[(size_t)d * 5 + j]);  // self term
    int i = off;
    for (; i + 4 <= end; i += 4) {
        int s0 = __ldg(sorted_src + i);
        int s1 = __ldg(sorted_src + i + 1);
        int s2 = __ldg(sorted_src + i + 2);
        int s3 = __ldg(sorted_src + i + 3);
        uint4 a = y4[(size_t)s0 * 5 + j];
        uint4 b = y4[(size_t)s1 * 5 + j];
        uint4 c = y4[(size_t)s2 * 5 + j];
        uint4 e = y4[(size_t)s3 * 5 + j];
        acc8(acc, a); acc8(acc, b); acc8(acc, c); acc8(acc, e);
    }
    if (i + 2 <= end) {
        int s0 = __ldg(sorted_src + i);
        int s1 = __ldg(sorted_src + i + 1);
        uint4 a = y4[(size_t)s0 * 5 + j];
        uint4 b = y4[(size_t)s1 * 5 + j];
        acc8(acc, a); acc8(acc, b);
        i += 2;
    }
    if (i < end) acc8(acc, y4[(size_t)__ldg(sorted_src + i) * 5 + j]);
    float dv = rsqrtf((float)deg[d] + 1.0f);
    const float* bb = b2 + j * 8;
    float* o = out + (size_t)d * COUT + j * 8;
    *(float4*)o       = make_float4(acc[0] * dv + bb[0], acc[1] * dv + bb[1],
                                    acc[2] * dv + bb[2], acc[3] * dv + bb[3]);
    *(float4*)(o + 4) = make_float4(acc[4] * dv + bb[4], acc[5] * dv + bb[5],
                                    acc[6] * dv + bb[6], acc[7] * dv + bb[7]);
}

// ======================= fused TF32 tensor-core GEMM =======================
#define XS_STR  68
#define BS1_STR 136
#define HS_STR  132
#define BS2_STR 72
#define GEMM_SMEM ((17408 + 9216) * 4)   // 106496 B

__global__ void __launch_bounds__(256, 2)
k_gemm(const float* __restrict__ aggx, const float* __restrict__ W1,
       const float* __restrict__ b1, const float* __restrict__ W2,
       const int* __restrict__ deg, __half* __restrict__ y2, int N) {
    extern __shared__ float sm[];
    float* xs  = sm;            // 128 x 68
    float* bs1 = sm + 8704;     // 64 x 136
    float* hs  = sm;            // 128 x 132 (aliases xs+bs1 after sync)
    float* bs2 = sm + 17408;    // 128 x 72

    const int tid = threadIdx.x;
    const int lane = tid & 31, w = tid >> 5;
    const int g = lane >> 2, t = lane & 3;
    const int row0 = blockIdx.x * 128;

    for (int i = tid; i < 64 * 128; i += 256) {
        int k = i >> 7, n = i & 127;
        bs1[k * BS1_STR + n] = tf32r(__ldg(W1 + i));
    }
    for (int i = tid; i < 128 * 72; i += 256) {
        int k = i / 72, n = i - k * 72;
        bs2[k * BS2_STR + n] = (n < COUT) ? tf32r(__ldg(W2 + k * COUT + n)) : 0.f;
    }
    {
        const float4* A4 = (const float4*)(aggx + (size_t)row0 * F_IN);
        for (int i = tid; i < 128 * 16; i += 256) {
            float4 v = A4[i];
            float* p = xs + (i >> 4) * XS_STR + (i & 15) * 4;
            p[0] = tf32r(v.x); p[1] = tf32r(v.y);
            p[2] = tf32r(v.z); p[3] = tf32r(v.w);
        }
    }
    __syncthreads();

    // ================= layer 1: warp tile 32 x 64, K = 64 =================
    const int m0 = (w & 3) * 32;
    const int n1 = (w >> 2) * 64;

    float c1[2][8][4];
    #pragma unroll
    for (int mf = 0; mf < 2; mf++)
        #pragma unroll
        for (int nf = 0; nf < 8; nf++)
            #pragma unroll
            for (int i = 0; i < 4; i++) c1[mf][nf][i] = 0.f;

    #pragma unroll
    for (int ks = 0; ks < 8; ks++) {
        int k8 = ks * 8;
        uint32_t a[2][4];
        #pragma unroll
        for (int mf = 0; mf < 2; mf++) {
            const float* p = xs + (m0 + mf * 16 + g) * XS_STR + k8 + t;
            a[mf][0] = __float_as_uint(p[0]);
            a[mf][1] = __float_as_uint(p[8 * XS_STR]);
            a[mf][2] = __float_as_uint(p[4]);
            a[mf][3] = __float_as_uint(p[8 * XS_STR + 4]);
        }
        #pragma unroll
        for (int nf = 0; nf < 8; nf++) {
            const float* bp = bs1 + (k8 + t) * BS1_STR + n1 + nf * 8 + g;
            uint32_t b0 = __float_as_uint(bp[0]);
            uint32_t b1v = __float_as_uint(bp[4 * BS1_STR]);
            mma_tf32(c1[0][nf], a[0], b0, b1v);
            mma_tf32(c1[1][nf], a[1], b0, b1v);
        }
    }
    __syncthreads();

    #pragma unroll
    for (int mf = 0; mf < 2; mf++) {
        int rb = m0 + mf * 16 + g;
        #pragma unroll
        for (int nf = 0; nf < 8; nf++) {
            int cb = n1 + nf * 8 + 2 * t;
            float bb0 = __ldg(b1 + cb), bb1 = __ldg(b1 + cb + 1);
            hs[rb * HS_STR + cb]           = tf32r(fmaxf(c1[mf][nf][0] + bb0, 0.f));
            hs[rb * HS_STR + cb + 1]       = tf32r(fmaxf(c1[mf][nf][1] + bb1, 0.f));
            hs[(rb + 8) * HS_STR + cb]     = tf32r(fmaxf(c1[mf][nf][2] + bb0, 0.f));
            hs[(rb + 8) * HS_STR + cb + 1] = tf32r(fmaxf(c1[mf][nf][3] + bb1, 0.f));
        }
    }
    __syncthreads();

    // ================= layer 2: warp tile 32 x 32, K = 128 =================
    const int n2 = (w >> 2) * 32;

    float c2[2][4][4];
    #pragma unroll
    for (int mf = 0; mf < 2; mf++)
        #pragma unroll
        for (int nf = 0; nf < 4; nf++)
            #pragma unroll
            for (int i = 0; i < 4; i++) c2[mf][nf][i] = 0.f;

    #pragma unroll 4
    for (int ks = 0; ks < 16; ks++) {
        int k8 = ks * 8;
        uint32_t a[2][4];
        #pragma unroll
        for (int mf = 0; mf < 2; mf++) {
            const float* p = hs + (m0 + mf * 16 + g) * HS_STR + k8 + t;
            a[mf][0] = __float_as_uint(p[0]);
            a[mf][1] = __float_as_uint(p[8 * HS_STR]);
            a[mf][2] = __float_as_uint(p[4]);
            a[mf][3] = __float_as_uint(p[8 * HS_STR + 4]);
        }
        #pragma unroll
        for (int nf = 0; nf < 4; nf++) {
            if (n2 + nf * 8 < COUT) {
                const float* bp = bs2 + (k8 + t) * BS2_STR + n2 + nf * 8 + g;
                uint32_t b0 = __float_as_uint(bp[0]);
                uint32_t b1v = __float_as_uint(bp[4 * BS2_STR]);
                mma_tf32(c2[0][nf], a[0], b0, b1v);
                mma_tf32(c2[1][nf], a[1], b0, b1v);
            }
        }
    }

    #pragma unroll
    for (int mf = 0; mf < 2; mf++) {
        int r0g = row0 + m0 + mf * 16 + g;
        int r1g = r0g + 8;
        float dv0 = 0.f, dv1 = 0.f;
        if (r0g < N) dv0 = rsqrtf((float)deg[r0g] + 1.0f);
        if (r1g < N) dv1 = rsqrtf((float)deg[r1g] + 1.0f);
        #pragma unroll
        for (int nf = 0; nf < 4; nf++) {
            int cb = n2 + nf * 8 + 2 * t;
            if (cb < COUT) {
                if (r0g < N) {
                    __half2 h = __floats2half2_rn(c2[mf][nf][0] * dv0, c2[mf][nf][1] * dv0);
                    *(__half2*)(y2 + (size_t)r0g * COUT + cb) = h;
                }
                if (r1g < N) {
                    __half2 h = __floats2half2_rn(c2[mf][nf][2] * dv1, c2[mf][nf][3] * dv1);
                    *(__half2*)(y2 + (size_t)r1g * COUT + cb) = h;
                }
            }
        }
    }
}

// ================================ launch ===================================
extern "C" void kernel_launch(void* const* d_in, const int* in_sizes, int n_in,
                              void* d_out, int out_size) {
    const float* x     = (const float*)d_in[0];
    const void*  edges = d_in[1];
    const float* W1    = (const float*)d_in[2];
    const float* b1    = (const float*)d_in[3];
    const float* W2    = (const float*)d_in[4];
    const float* b2    = (const float*)d_in[5];
    float* out = (float*)d_out;

    const int N = in_sizes[0] / F_IN;
    const int E = in_sizes[1] / 2;
    const int nchunks = (N + SCAN_CHUNK - 1) / SCAN_CHUNK;

    int *deg, *cursor, *offsets, *partials, *ssrc;
    __half *y1, *y2;
    float *aggx;
    cudaGetSymbolAddress((void**)&deg,      g_deg);
    cudaGetSymbolAddress((void**)&cursor,   g_cursor);
    cudaGetSymbolAddress((void**)&offsets,  g_offsets);
    cudaGetSymbolAddress((void**)&partials, g_partials);
    cudaGetSymbolAddress((void**)&ssrc,     g_sorted_src);
    cudaGetSymbolAddress((void**)&y1,       g_y1);
    cudaGetSymbolAddress((void**)&aggx,     g_aggx);
    cudaGetSymbolAddress((void**)&y2,       g_y2);

    cudaFuncSetAttribute(k_gemm, cudaFuncAttributeMaxDynamicSharedMemorySize, GEMM_SMEM);

    k_zero<<<(N + 255) / 256, 256>>>(deg, cursor, (const int*)edges, N);       // 0
    k_hist<<<(E + 255) / 256, 256>>>(edges, deg, E);                           // 1
    k_scan_a<<<nchunks, 256>>>(deg, partials, N);                              // 2
    k_scan_c<<<nchunks, 256>>>(deg, partials, offsets, nchunks, N);            // 3
    k_place<<<(E + 255) / 256, 256>>>(edges, offsets, cursor, ssrc, E);        // 4
    k_y1<<<(N * 16 + 255) / 256, 256>>>(x, deg, y1, N);                        // 5
    k_agg1<<<(N * 8 + 255) / 256, 256>>>(ssrc, offsets, deg, y1, aggx, N);     // 6
    k_gemm<<<(N + 127) / 128, 256, GEMM_SMEM>>>(aggx, W1, b1, W2, deg, y2, N); // 7
    k_agg2<<<(N * 5 + 255) / 256, 256>>>(ssrc, offsets, deg, y2, b2, out, N);  // 8
}